// round 9
// baseline (speedup 1.0000x reference)
#include <cuda_runtime.h>
#include <math.h>

#define H 512
#define W 512
#define PLANE (H*W)
#define NB 8
#define NPL 16
#define NELEM (NB*PLANE)
#define EPSF 1e-6f
#define BIG 1e30f

// 2-col x 2-row per thread: 56 useful cols per warp, 32 rows per seg
#define STRIPSP 10
#define SEGSP   16
#define SEGH    32
#define BLK_WARPS 4
#define WARPSP (NPL*STRIPSP*SEGSP)      // 2560
#define GRIDP  (WARPSP/BLK_WARPS)       // 640

__device__ float g_bufA[NPL*PLANE];
__device__ float g_bufB[NPL*PLANE];
__device__ float g_skel[NPL*PLANE];
__device__ float g_acc[96];

__device__ __forceinline__ float sigmoidf_(float x) {
    return 1.0f / (1.0f + __expf(-x));
}

__device__ __forceinline__ float focal_elem(float x, float t) {
    float bce = fmaxf(x, 0.0f) - x * t + log1pf(__expf(-fabsf(x)));
    float p   = sigmoidf_(x);
    float pt  = p * t + (1.0f - p) * (1.0f - t);
    float at  = 0.25f * t + 0.75f * (1.0f - t);
    float om  = 1.0f - pt;
    return at * om * om * bce;
}

__device__ __forceinline__ float blk_sum(float v, float* sh) {
    int tid = threadIdx.x;
    #pragma unroll
    for (int o = 16; o > 0; o >>= 1) v += __shfl_down_sync(0xffffffffu, v, o);
    if ((tid & 31) == 0) sh[tid >> 5] = v;
    __syncthreads();
    float r = 0.0f;
    if (tid < 32) {
        r = (tid < (int)(blockDim.x >> 5)) ? sh[tid] : 0.0f;
        #pragma unroll
        for (int o = 16; o > 0; o >>= 1) r += __shfl_down_sync(0xffffffffu, r, o);
    }
    __syncthreads();
    return r;
}

// pairwise 5-pt cross erode over 64 warp columns (cols x0=2*lane, x1=2*lane+1)
__device__ __forceinline__ float2 erode5p(float2 m, float2 c, float2 p) {
    float lm = __shfl_up_sync(0xffffffffu, c.y, 1);
    float rm = __shfl_down_sync(0xffffffffu, c.x, 1);
    float2 r;
    r.x = fminf(fminf(fminf(m.x, p.x), c.x), fminf(lm, c.y));
    r.y = fminf(fminf(fminf(m.y, p.y), c.y), fminf(c.x, rm));
    return r;
}
// pairwise 3x3 max (open)
__device__ __forceinline__ float2 open3p(float2 m, float2 c, float2 p) {
    float2 v;
    v.x = fmaxf(fmaxf(m.x, p.x), c.x);
    v.y = fmaxf(fmaxf(m.y, p.y), c.y);
    float lm = __shfl_up_sync(0xffffffffu, v.y, 1);
    float rm = __shfl_down_sync(0xffffffffu, v.x, 1);
    float2 r;
    r.x = fmaxf(v.x, fmaxf(lm, v.y));
    r.y = fmaxf(v.y, fmaxf(v.x, rm));
    return r;
}
__device__ __forceinline__ float2 padv(float2 v, bool rowOK, bool x0OK, bool x1OK, float pad) {
    float2 r;
    r.x = (rowOK && x0OK) ? v.x : pad;
    r.y = (rowOK && x1OK) ? v.y : pad;
    return r;
}

__global__ void zero_acc_kernel() {
    if (threadIdx.x < 96) g_acc[threadIdx.x] = 0.0f;
}

// ---------------------------------------------------------------------------
// Pass A (float4-vectorized); seeds g_bufA only.
// ---------------------------------------------------------------------------
__global__ void pass_a_kernel(const float4* __restrict__ ml, const float4* __restrict__ sl,
                              const float4* __restrict__ ul, const float4* __restrict__ jl,
                              const float4* __restrict__ el, const float4* __restrict__ ap,
                              const float4* __restrict__ mk, const float4* __restrict__ sk,
                              const float4* __restrict__ jn, const float4* __restrict__ ep,
                              const float4* __restrict__ at, const float4* __restrict__ un) {
    const int Q = PLANE / 4;
    int b   = blockIdx.y;
    int tid = threadIdx.x;
    int base = b * Q;

    float4* __restrict__ bufap = (float4*)g_bufA;

    float di = 0.f, dp = 0.f, dt = 0.f;
    float si = 0.f, spp = 0.f, stt = 0.f;
    float fm = 0.f, fj = 0.f, fe = 0.f;
    float sl1 = 0.f, msum = 0.f, usum = 0.f;

    for (int i = blockIdx.x * blockDim.x + tid; i < Q; i += gridDim.x * blockDim.x) {
        int g = base + i;
        float4 xm4 = ml[g];
        float4 tm4 = mk[g];
        float4 pm4, tmc4;

        #pragma unroll
        for (int u = 0; u < 4; u++) {
            float xm = ((float*)&xm4)[u];
            float tm = ((float*)&tm4)[u];
            float pm = sigmoidf_(xm);
            ((float*)&pm4)[u] = pm;
            ((float*)&tmc4)[u] = fminf(fmaxf(tm, 0.0f), 1.0f);
            di += pm * tm;  dp += pm;  dt += tm;
            fm += focal_elem(xm, tm);
        }
        bufap[g] = pm4;
        bufap[(8 + b) * Q + i] = tmc4;

        float4 ts4 = sk[g];
        float4 ps4 = sl[g];
        float4 jl4 = jl[g], jn4 = jn[g], el4 = el[g], ep4 = ep[g];
        float4 ul4 = ul[g], un4 = un[g];
        float4 ap0 = ap[b * 2 * Q + i], ap1 = ap[b * 2 * Q + Q + i];
        float4 at0 = at[b * 2 * Q + i], at1 = at[b * 2 * Q + Q + i];

        #pragma unroll
        for (int u = 0; u < 4; u++) {
            float ts = ((float*)&ts4)[u];
            float psk = sigmoidf_(((float*)&ps4)[u]);
            si += psk * ts;  spp += psk;  stt += ts;

            fj += focal_elem(((float*)&jl4)[u], ((float*)&jn4)[u]);
            fe += focal_elem(((float*)&el4)[u], ((float*)&ep4)[u]);

            float pu = sigmoidf_(((float*)&ul4)[u]);
            float du = pu - ((float*)&un4)[u];
            usum += du * du;

            float m = ts;
            float d0 = ((float*)&ap0)[u] * m - ((float*)&at0)[u] * m;
            float ad0 = fabsf(d0);
            sl1 += (ad0 < 1.0f) ? 0.5f * d0 * d0 : ad0 - 0.5f;
            float d1 = ((float*)&ap1)[u] * m - ((float*)&at1)[u] * m;
            float ad1 = fabsf(d1);
            sl1 += (ad1 < 1.0f) ? 0.5f * d1 * d1 : ad1 - 0.5f;
            msum += 2.0f * m;
        }
    }

    __shared__ float sh[32];
    float vals[12] = {di, dp, dt, si, spp, stt, fm, fj, fe, sl1, msum, usum};
    #pragma unroll
    for (int k = 0; k < 12; k++) {
        float r = blk_sum(vals[k], sh);
        if (tid == 0) {
            int a = (k < 6) ? (b * 6 + k) : (42 + k);
            atomicAdd(&g_acc[a], r);
        }
    }
}

// ---------------------------------------------------------------------------
// Fused double-iteration skeletonize, 2 cols x 2 rows per thread (fast path).
//  MODE 0: init + iters 1,2  (skel pure write)
//  MODE 1: two iterations     (skel RMW)
//  MODE 2: final two iters + clDice accumulation (no global writes)
// ---------------------------------------------------------------------------
template<int MODE>
__global__ void __launch_bounds__(128, 7) skel2_kernel(int useA,
                                                       const float* __restrict__ ml,
                                                       const float* __restrict__ mk) {
    const float* __restrict__ cur = useA ? g_bufA : g_bufB;
    float* __restrict__ nxt = useA ? g_bufB : g_bufA;

    int lane = threadIdx.x & 31;
    int wg = blockIdx.x * BLK_WARPS + (threadIdx.x >> 5);
    int plane = wg / (STRIPSP * SEGSP);
    int rem = wg - plane * (STRIPSP * SEGSP);
    int strip = rem / SEGSP;
    int seg = rem & (SEGSP - 1);

    int x0 = strip * 56 - 4 + 2 * lane;
    int x1 = x0 + 1;
    bool x0OK = (unsigned)x0 < (unsigned)W;
    bool x1OK = (unsigned)x1 < (unsigned)W;
    bool laneOut = (lane >= 2) && (lane <= 29);
    bool out0 = laneOut && x0OK;
    bool out1 = laneOut && x1OK;
    int y0 = seg * SEGH;
    int base = plane * PLANE;

    const float* __restrict__ cp = cur + base + x0;
    float* __restrict__ skp = g_skel + base + x0;
    float* __restrict__ nxp = nxt + base + x0;

    bool isPred = (plane < 8);
    int b8 = isPred ? plane : (plane - 8);
    const float* __restrict__ pp = (isPred ? mk : ml) + b8 * PLANE + x0;
    float accP = 0.0f, accS = 0.0f;

    bool fast = (strip >= 1) && (strip <= 8) && (seg >= 1) && (seg <= 14);

    if (fast) {
        // ---------------- prologue ----------------
        float2 c_[10];
        #pragma unroll
        for (int i = 0; i < 10; i++) c_[i] = *(const float2*)(cp + (y0 - 4 + i) * W);
        float2 e1r[6];
        #pragma unroll
        for (int k = 0; k < 6; k++) e1r[k] = erode5p(c_[k], c_[k + 1], c_[k + 2]);
        float2 e2r[4];
        #pragma unroll
        for (int k = 0; k < 4; k++) e2r[k] = erode5p(e1r[k], e1r[k + 1], e1r[k + 2]);
        float2 e3_m = erode5p(e2r[0], e2r[1], e2r[2]);
        float2 e3_0 = erode5p(e2r[1], e2r[2], e2r[3]);

        float2 c0 = c_[4], c1 = c_[5], c2 = c_[6], c3 = c_[7], c4 = c_[8], c5 = c_[9];
        float2 e1_m = e1r[2], e1_0 = e1r[3], e1_1 = e1r[4], e1_2 = e1r[5];
        float2 e2_m = e2r[1], e2_0 = e2r[2], e2_1 = e2r[3];

        // ---------------- main loop: 2 rows / step ----------------
        #pragma unroll 2
        for (int y = y0; y < y0 + SEGH; y += 2) {
            float2 c6 = *(const float2*)(cp + (y + 6) * W);
            float2 c7 = *(const float2*)(cp + (y + 7) * W);

            // two independent erode chains
            float2 e1_3 = erode5p(c2, c3, c4);
            float2 e1_4 = erode5p(c3, c4, c5);
            float2 e2_2 = erode5p(e1_1, e1_2, e1_3);
            float2 e2_3 = erode5p(e1_2, e1_3, e1_4);
            float2 e3_1 = erode5p(e2_0, e2_1, e2_2);
            float2 e3_2 = erode5p(e2_1, e2_2, e2_3);

            float2 openA0 = open3p(e2_m, e2_0, e2_1);
            float2 openA1 = open3p(e2_0, e2_1, e2_2);
            float2 openB0 = open3p(e3_m, e3_0, e3_1);
            float2 openB1 = open3p(e3_0, e3_1, e3_2);

            float2 s0, s1;
            if (MODE == 0) {
                float2 openI0 = open3p(e1_m, e1_0, e1_1);
                float2 openI1 = open3p(e1_0, e1_1, e1_2);
                s0.x = fmaxf(c0.x - openI0.x, 0.0f);
                s0.y = fmaxf(c0.y - openI0.y, 0.0f);
                s1.x = fmaxf(c1.x - openI1.x, 0.0f);
                s1.y = fmaxf(c1.y - openI1.y, 0.0f);
            } else {
                s0 = *(const float2*)(skp + y * W);
                s1 = *(const float2*)(skp + (y + 1) * W);
            }

            // row y
            {
                float dA0 = fmaxf(e1_0.x - openA0.x, 0.0f);
                float dA1 = fmaxf(e1_0.y - openA0.y, 0.0f);
                s0.x += fmaxf(dA0 - s0.x * dA0, 0.0f);
                s0.y += fmaxf(dA1 - s0.y * dA1, 0.0f);
                float dB0 = fmaxf(e2_0.x - openB0.x, 0.0f);
                float dB1 = fmaxf(e2_0.y - openB0.y, 0.0f);
                s0.x += fmaxf(dB0 - s0.x * dB0, 0.0f);
                s0.y += fmaxf(dB1 - s0.y * dB1, 0.0f);
            }
            // row y+1
            {
                float dA0 = fmaxf(e1_1.x - openA1.x, 0.0f);
                float dA1 = fmaxf(e1_1.y - openA1.y, 0.0f);
                s1.x += fmaxf(dA0 - s1.x * dA0, 0.0f);
                s1.y += fmaxf(dA1 - s1.y * dA1, 0.0f);
                float dB0 = fmaxf(e2_1.x - openB1.x, 0.0f);
                float dB1 = fmaxf(e2_1.y - openB1.y, 0.0f);
                s1.x += fmaxf(dB0 - s1.x * dB0, 0.0f);
                s1.y += fmaxf(dB1 - s1.y * dB1, 0.0f);
            }

            if (MODE == 2) {
                if (laneOut) {
                    float2 t0 = *(const float2*)(pp + y * W);
                    float2 t1 = *(const float2*)(pp + (y + 1) * W);
                    float u00 = isPred ? fminf(fmaxf(t0.x, 0.0f), 1.0f) : sigmoidf_(t0.x);
                    float u01 = isPred ? fminf(fmaxf(t0.y, 0.0f), 1.0f) : sigmoidf_(t0.y);
                    float u10 = isPred ? fminf(fmaxf(t1.x, 0.0f), 1.0f) : sigmoidf_(t1.x);
                    float u11 = isPred ? fminf(fmaxf(t1.y, 0.0f), 1.0f) : sigmoidf_(t1.y);
                    float p00 = fminf(fmaxf(s0.x, 0.0f), 1.0f);
                    float p01 = fminf(fmaxf(s0.y, 0.0f), 1.0f);
                    float p10 = fminf(fmaxf(s1.x, 0.0f), 1.0f);
                    float p11 = fminf(fmaxf(s1.y, 0.0f), 1.0f);
                    accP += p00 * u00 + p01 * u01 + p10 * u10 + p11 * u11;
                    accS += p00 + p01 + p10 + p11;
                }
            } else if (laneOut) {
                *(float2*)(nxp + y * W) = e2_0;
                *(float2*)(nxp + (y + 1) * W) = e2_1;
                *(float2*)(skp + y * W) = s0;
                *(float2*)(skp + (y + 1) * W) = s1;
            }

            c0 = c2; c1 = c3; c2 = c4; c3 = c5; c4 = c6; c5 = c7;
            e1_m = e1_1; e1_0 = e1_2; e1_1 = e1_3; e1_2 = e1_4;
            e2_m = e2_1; e2_0 = e2_2; e2_1 = e2_3;
            e3_m = e3_1; e3_0 = e3_2;
        }
    } else {
        // ---------------- general (boundary) path: 1 row / step ----------------
        float2 c_[10];
        #pragma unroll
        for (int i = 0; i < 10; i++) {
            int yy = y0 - 4 + i;
            bool rOK = (unsigned)yy < (unsigned)H;
            float2 v;
            v.x = (rOK && x0OK) ? cp[yy * W] : BIG;
            v.y = (rOK && x1OK) ? cp[yy * W + 1] : BIG;
            c_[i] = v;
        }
        float2 e1r[6];
        #pragma unroll
        for (int k = 0; k < 6; k++) {
            int r = y0 - 3 + k;
            e1r[k] = padv(erode5p(c_[k], c_[k + 1], c_[k + 2]),
                          (unsigned)r < (unsigned)H, x0OK, x1OK, BIG);
        }
        float2 e2r[4];
        #pragma unroll
        for (int k = 0; k < 4; k++) e2r[k] = erode5p(e1r[k], e1r[k + 1], e1r[k + 2]);

        float2 t0v = padv(e2r[0], (y0 - 2) >= 0, x0OK, x1OK, BIG);
        float2 t1v = padv(e2r[1], (y0 - 1) >= 0, x0OK, x1OK, BIG);
        float2 t2v = padv(e2r[2], true, x0OK, x1OK, BIG);
        float2 t3v = padv(e2r[3], true, x0OK, x1OK, BIG);
        float2 e3_m = padv(erode5p(t0v, t1v, t2v), (y0 - 1) >= 0, x0OK, x1OK, -BIG);
        float2 e3_0 = padv(erode5p(t1v, t2v, t3v), true, x0OK, x1OK, -BIG);

        float2 c0 = c_[4], c1 = c_[5], c2 = c_[6], c3 = c_[7], c4 = c_[8], c5 = c_[9];
        float2 e1_m = e1r[2], e1_0 = e1r[3], e1_1 = e1r[4], e1_2 = e1r[5];
        float2 e2_m = e2r[1], e2_0 = e2r[2], e2_1 = e2r[3];

        #pragma unroll 4
        for (int y = y0; y < y0 + SEGH; y++) {
            int yl = y + 6;
            bool rl = (unsigned)yl < (unsigned)H;
            float2 c6;
            c6.x = (rl && x0OK) ? cp[yl * W] : BIG;
            c6.y = (rl && x1OK) ? cp[yl * W + 1] : BIG;

            float2 e1_3 = padv(erode5p(c2, c3, c4), (unsigned)(y + 3) < (unsigned)H, x0OK, x1OK, BIG);
            float2 e2_2 = erode5p(e1_1, e1_2, e1_3);

            float2 a = padv(e2_0, true, x0OK, x1OK, BIG);
            float2 b = padv(e2_1, (unsigned)(y + 1) < (unsigned)H, x0OK, x1OK, BIG);
            float2 d = padv(e2_2, (unsigned)(y + 2) < (unsigned)H, x0OK, x1OK, BIG);
            float2 e3_1 = padv(erode5p(a, b, d), (unsigned)(y + 1) < (unsigned)H, x0OK, x1OK, -BIG);

            float2 ma = padv(e2_m, (y - 1) >= 0, x0OK, x1OK, -BIG);
            float2 mb = padv(e2_0, true, x0OK, x1OK, -BIG);
            float2 mc = padv(e2_1, (unsigned)(y + 1) < (unsigned)H, x0OK, x1OK, -BIG);
            float2 openA = open3p(ma, mb, mc);
            float2 openB = open3p(e3_m, e3_0, e3_1);

            float2 s;
            if (MODE == 0) {
                float2 ia = padv(e1_m, (y - 1) >= 0, x0OK, x1OK, -BIG);
                float2 ib = padv(e1_0, true, x0OK, x1OK, -BIG);
                float2 ic = padv(e1_1, (unsigned)(y + 1) < (unsigned)H, x0OK, x1OK, -BIG);
                float2 openI = open3p(ia, ib, ic);
                s.x = fmaxf(c0.x - openI.x, 0.0f);
                s.y = fmaxf(c0.y - openI.y, 0.0f);
            } else {
                s.x = out0 ? skp[y * W] : 0.0f;
                s.y = out1 ? skp[y * W + 1] : 0.0f;
            }
            float dA0 = fmaxf(e1_0.x - openA.x, 0.0f);
            float dA1 = fmaxf(e1_0.y - openA.y, 0.0f);
            s.x += fmaxf(dA0 - s.x * dA0, 0.0f);
            s.y += fmaxf(dA1 - s.y * dA1, 0.0f);
            float dB0 = fmaxf(e2_0.x - openB.x, 0.0f);
            float dB1 = fmaxf(e2_0.y - openB.y, 0.0f);
            s.x += fmaxf(dB0 - s.x * dB0, 0.0f);
            s.y += fmaxf(dB1 - s.y * dB1, 0.0f);

            if (MODE == 2) {
                if (out0) {
                    float raw = pp[y * W];
                    float t = isPred ? fminf(fmaxf(raw, 0.0f), 1.0f) : sigmoidf_(raw);
                    float ps = fminf(fmaxf(s.x, 0.0f), 1.0f);
                    accP += ps * t;  accS += ps;
                }
                if (out1) {
                    float raw = pp[y * W + 1];
                    float t = isPred ? fminf(fmaxf(raw, 0.0f), 1.0f) : sigmoidf_(raw);
                    float ps = fminf(fmaxf(s.y, 0.0f), 1.0f);
                    accP += ps * t;  accS += ps;
                }
            } else {
                if (out0) { nxp[y * W] = e2_0.x;      skp[y * W] = s.x; }
                if (out1) { nxp[y * W + 1] = e2_0.y;  skp[y * W + 1] = s.y; }
            }

            c0 = c1; c1 = c2; c2 = c3; c3 = c4; c4 = c5; c5 = c6;
            e1_m = e1_0; e1_0 = e1_1; e1_1 = e1_2; e1_2 = e1_3;
            e2_m = e2_0; e2_0 = e2_1; e2_1 = e2_2;
            e3_m = e3_0; e3_0 = e3_1;
        }
    }

    if (MODE == 2) {
        #pragma unroll
        for (int o = 16; o > 0; o >>= 1) {
            accP += __shfl_down_sync(0xffffffffu, accP, o);
            accS += __shfl_down_sync(0xffffffffu, accS, o);
        }
        if (lane == 0) {
            int idx = 54 + b8 * 4 + (isPred ? 0 : 2);
            atomicAdd(&g_acc[idx], accP);
            atomicAdd(&g_acc[idx + 1], accS);
        }
    }
}

// ---------------------------------------------------------------------------
__global__ void finalize_kernel(float* __restrict__ out) {
    const float N = (float)NELEM;
    float dice_m = 0.f, dice_s = 0.f, cl = 0.f;
    #pragma unroll
    for (int b = 0; b < NB; b++) {
        float im = g_acc[b * 6 + 0], pm = g_acc[b * 6 + 1], tm = g_acc[b * 6 + 2];
        dice_m += (2.0f * im + EPSF) / (pm + tm + EPSF);
        float is = g_acc[b * 6 + 3], ps = g_acc[b * 6 + 4], ts = g_acc[b * 6 + 5];
        dice_s += (2.0f * is + EPSF) / (ps + ts + EPSF);
        float c0 = g_acc[54 + b * 4 + 0], c1 = g_acc[54 + b * 4 + 1];
        float c2 = g_acc[54 + b * 4 + 2], c3 = g_acc[54 + b * 4 + 3];
        float prec = c0 / (c1 + EPSF);
        float sens = c2 / (c3 + EPSF);
        cl += (2.0f * prec * sens + EPSF) / (prec + sens + EPSF);
    }
    dice_m *= 0.125f;  dice_s *= 0.125f;  cl *= 0.125f;

    float mask_loss     = (1.0f - dice_m) + g_acc[48] / N;
    float skeleton_loss = 1.0f - dice_s;
    float topology_loss = 1.0f - cl;
    float node_loss     = 0.5f * (g_acc[49] / N + g_acc[50] / N);
    float msum          = g_acc[52];
    float aff_loss      = (msum == 0.0f) ? 0.0f : g_acc[51] / fmaxf(msum, 1.0f);
    float unc_loss      = g_acc[53] / N;

    out[0] = 1.0f * mask_loss + 1.0f * skeleton_loss + 0.5f * topology_loss +
             0.5f * node_loss + 0.5f * aff_loss + 0.1f * unc_loss;
}

// ---------------------------------------------------------------------------
extern "C" void kernel_launch(void* const* d_in, const int* in_sizes, int n_in,
                              void* d_out, int out_size) {
    const float* ml = (const float*)d_in[0];
    const float* mk = (const float*)d_in[6];
    float* out = (float*)d_out;

    zero_acc_kernel<<<1, 96>>>();

    dim3 gA(64, NB);
    pass_a_kernel<<<gA, 256>>>(
        (const float4*)d_in[0], (const float4*)d_in[1], (const float4*)d_in[2],
        (const float4*)d_in[3], (const float4*)d_in[4], (const float4*)d_in[5],
        (const float4*)d_in[6], (const float4*)d_in[7], (const float4*)d_in[8],
        (const float4*)d_in[9], (const float4*)d_in[10], (const float4*)d_in[11]);

    // iters 1,2 (init)  A -> B
    skel2_kernel<0><<<GRIDP, 128>>>(1, ml, mk);
    // iters 3,4  B -> A ; 5,6  A -> B ; 7,8  B -> A
    skel2_kernel<1><<<GRIDP, 128>>>(0, ml, mk);
    skel2_kernel<1><<<GRIDP, 128>>>(1, ml, mk);
    skel2_kernel<1><<<GRIDP, 128>>>(0, ml, mk);
    // iters 9,10 + clDice reduce, read A, no writes
    skel2_kernel<2><<<GRIDP, 128>>>(1, ml, mk);

    finalize_kernel<<<1, 1>>>(out);
}

// round 10
// speedup vs baseline: 1.1776x; 1.1776x over previous
#include <cuda_runtime.h>
#include <math.h>

#define H 512
#define W 512
#define PLANE (H*W)
#define NB 8
#define NPL 16
#define NELEM (NB*PLANE)
#define EPSF 1e-6f
#define BIG 1e30f

// 2-col-per-thread skeletonize layout: 56 useful cols per warp, 16 rows per seg
#define STRIPSP 10
#define SEGSP   32
#define SEGH    16
#define BLK_WARPS 2
#define WARPSP (NPL*STRIPSP*SEGSP)      // 5120
#define GRIDP  (WARPSP/BLK_WARPS)       // 2560

__device__ float g_bufA[NPL*PLANE];
__device__ float g_bufB[NPL*PLANE];
__device__ float g_skel[NPL*PLANE];
__device__ float g_acc[96];

__device__ __forceinline__ float sigmoidf_(float x) {
    return 1.0f / (1.0f + __expf(-x));
}

__device__ __forceinline__ float focal_elem(float x, float t) {
    float bce = fmaxf(x, 0.0f) - x * t + log1pf(__expf(-fabsf(x)));
    float p   = sigmoidf_(x);
    float pt  = p * t + (1.0f - p) * (1.0f - t);
    float at  = 0.25f * t + 0.75f * (1.0f - t);
    float om  = 1.0f - pt;
    return at * om * om * bce;
}

__device__ __forceinline__ float blk_sum(float v, float* sh) {
    int tid = threadIdx.x;
    #pragma unroll
    for (int o = 16; o > 0; o >>= 1) v += __shfl_down_sync(0xffffffffu, v, o);
    if ((tid & 31) == 0) sh[tid >> 5] = v;
    __syncthreads();
    float r = 0.0f;
    if (tid < 32) {
        r = (tid < (int)(blockDim.x >> 5)) ? sh[tid] : 0.0f;
        #pragma unroll
        for (int o = 16; o > 0; o >>= 1) r += __shfl_down_sync(0xffffffffu, r, o);
    }
    __syncthreads();
    return r;
}

// pairwise 5-pt cross erode over 64 warp columns (cols x0=2*lane, x1=2*lane+1)
__device__ __forceinline__ float2 erode5p(float2 m, float2 c, float2 p) {
    float lm = __shfl_up_sync(0xffffffffu, c.y, 1);
    float rm = __shfl_down_sync(0xffffffffu, c.x, 1);
    float2 r;
    r.x = fminf(fminf(fminf(m.x, p.x), c.x), fminf(lm, c.y));
    r.y = fminf(fminf(fminf(m.y, p.y), c.y), fminf(c.x, rm));
    return r;
}
// pairwise 3x3 max (open)
__device__ __forceinline__ float2 open3p(float2 m, float2 c, float2 p) {
    float2 v;
    v.x = fmaxf(fmaxf(m.x, p.x), c.x);
    v.y = fmaxf(fmaxf(m.y, p.y), c.y);
    float lm = __shfl_up_sync(0xffffffffu, v.y, 1);
    float rm = __shfl_down_sync(0xffffffffu, v.x, 1);
    float2 r;
    r.x = fmaxf(v.x, fmaxf(lm, v.y));
    r.y = fmaxf(v.y, fmaxf(v.x, rm));
    return r;
}
__device__ __forceinline__ float2 padv(float2 v, bool rowOK, bool x0OK, bool x1OK, float pad) {
    float2 r;
    r.x = (rowOK && x0OK) ? v.x : pad;
    r.y = (rowOK && x1OK) ? v.y : pad;
    return r;
}

__global__ void zero_acc_kernel() {
    if (threadIdx.x < 96) g_acc[threadIdx.x] = 0.0f;
}

// ---------------------------------------------------------------------------
// Pass A (float4-vectorized); seeds g_bufA only.
// ---------------------------------------------------------------------------
__global__ void pass_a_kernel(const float4* __restrict__ ml, const float4* __restrict__ sl,
                              const float4* __restrict__ ul, const float4* __restrict__ jl,
                              const float4* __restrict__ el, const float4* __restrict__ ap,
                              const float4* __restrict__ mk, const float4* __restrict__ sk,
                              const float4* __restrict__ jn, const float4* __restrict__ ep,
                              const float4* __restrict__ at, const float4* __restrict__ un) {
    const int Q = PLANE / 4;
    int b   = blockIdx.y;
    int tid = threadIdx.x;
    int base = b * Q;

    float4* __restrict__ bufap = (float4*)g_bufA;

    float di = 0.f, dp = 0.f, dt = 0.f;
    float si = 0.f, spp = 0.f, stt = 0.f;
    float fm = 0.f, fj = 0.f, fe = 0.f;
    float sl1 = 0.f, msum = 0.f, usum = 0.f;

    for (int i = blockIdx.x * blockDim.x + tid; i < Q; i += gridDim.x * blockDim.x) {
        int g = base + i;
        float4 xm4 = ml[g];
        float4 tm4 = mk[g];
        float4 pm4, tmc4;

        #pragma unroll
        for (int u = 0; u < 4; u++) {
            float xm = ((float*)&xm4)[u];
            float tm = ((float*)&tm4)[u];
            float pm = sigmoidf_(xm);
            ((float*)&pm4)[u] = pm;
            ((float*)&tmc4)[u] = fminf(fmaxf(tm, 0.0f), 1.0f);
            di += pm * tm;  dp += pm;  dt += tm;
            fm += focal_elem(xm, tm);
        }
        bufap[g] = pm4;
        bufap[(8 + b) * Q + i] = tmc4;

        float4 ts4 = sk[g];
        float4 ps4 = sl[g];
        float4 jl4 = jl[g], jn4 = jn[g], el4 = el[g], ep4 = ep[g];
        float4 ul4 = ul[g], un4 = un[g];
        float4 ap0 = ap[b * 2 * Q + i], ap1 = ap[b * 2 * Q + Q + i];
        float4 at0 = at[b * 2 * Q + i], at1 = at[b * 2 * Q + Q + i];

        #pragma unroll
        for (int u = 0; u < 4; u++) {
            float ts = ((float*)&ts4)[u];
            float psk = sigmoidf_(((float*)&ps4)[u]);
            si += psk * ts;  spp += psk;  stt += ts;

            fj += focal_elem(((float*)&jl4)[u], ((float*)&jn4)[u]);
            fe += focal_elem(((float*)&el4)[u], ((float*)&ep4)[u]);

            float pu = sigmoidf_(((float*)&ul4)[u]);
            float du = pu - ((float*)&un4)[u];
            usum += du * du;

            float m = ts;
            float d0 = ((float*)&ap0)[u] * m - ((float*)&at0)[u] * m;
            float ad0 = fabsf(d0);
            sl1 += (ad0 < 1.0f) ? 0.5f * d0 * d0 : ad0 - 0.5f;
            float d1 = ((float*)&ap1)[u] * m - ((float*)&at1)[u] * m;
            float ad1 = fabsf(d1);
            sl1 += (ad1 < 1.0f) ? 0.5f * d1 * d1 : ad1 - 0.5f;
            msum += 2.0f * m;
        }
    }

    __shared__ float sh[32];
    float vals[12] = {di, dp, dt, si, spp, stt, fm, fj, fe, sl1, msum, usum};
    #pragma unroll
    for (int k = 0; k < 12; k++) {
        float r = blk_sum(vals[k], sh);
        if (tid == 0) {
            int a = (k < 6) ? (b * 6 + k) : (42 + k);
            atomicAdd(&g_acc[a], r);
        }
    }
}

// ---------------------------------------------------------------------------
// Fused double-iteration skeletonize, 2 columns per thread, 64-thread blocks.
//  MODE 0: init + iters 1,2  (skel pure write)
//  MODE 1: two iterations     (skel RMW)
//  MODE 2: final two iters + clDice accumulation (no global writes)
// ---------------------------------------------------------------------------
template<int MODE>
__global__ void __launch_bounds__(64, 18) skel2_kernel(int useA,
                                                       const float* __restrict__ ml,
                                                       const float* __restrict__ mk) {
    const float* __restrict__ cur = useA ? g_bufA : g_bufB;
    float* __restrict__ nxt = useA ? g_bufB : g_bufA;

    int lane = threadIdx.x & 31;
    int wg = blockIdx.x * BLK_WARPS + (threadIdx.x >> 5);
    int plane = wg / (STRIPSP * SEGSP);
    int rem = wg - plane * (STRIPSP * SEGSP);
    int strip = rem / SEGSP;
    int seg = rem & (SEGSP - 1);

    int x0 = strip * 56 - 4 + 2 * lane;       // even
    int x1 = x0 + 1;
    bool x0OK = (unsigned)x0 < (unsigned)W;
    bool x1OK = (unsigned)x1 < (unsigned)W;
    bool laneOut = (lane >= 2) && (lane <= 29);
    bool out0 = laneOut && x0OK;
    bool out1 = laneOut && x1OK;
    int y0 = seg * SEGH;
    int base = plane * PLANE;

    const float* __restrict__ cp = cur + base + x0;
    float* __restrict__ skp = g_skel + base + x0;
    float* __restrict__ nxp = nxt + base + x0;

    // clDice partner source (MODE 2): plane<8 -> clip(mask), plane>=8 -> sigmoid(mask_logits)
    bool isPred = (plane < 8);
    int b8 = isPred ? plane : (plane - 8);
    const float* __restrict__ pp = (isPred ? mk : ml) + b8 * PLANE + x0;
    float accP = 0.0f, accS = 0.0f;

    bool fast = (strip >= 1) && (strip <= 8) && (seg >= 1) && (seg <= 30);

    float2 c0, c1, c2, c3, c4, c5;
    float2 e1_m, e1_0, e1_1, e1_2;
    float2 e2_m, e2_0, e2_1;
    float2 e3_m, e3_0;

    if (fast) {
        float2 c_[10];
        #pragma unroll
        for (int i = 0; i < 10; i++) c_[i] = *(const float2*)(cp + (y0 - 4 + i) * W);
        float2 e1r[6];
        #pragma unroll
        for (int k = 0; k < 6; k++) e1r[k] = erode5p(c_[k], c_[k + 1], c_[k + 2]);
        float2 e2r[4];
        #pragma unroll
        for (int k = 0; k < 4; k++) e2r[k] = erode5p(e1r[k], e1r[k + 1], e1r[k + 2]);
        e3_m = erode5p(e2r[0], e2r[1], e2r[2]);
        e3_0 = erode5p(e2r[1], e2r[2], e2r[3]);

        c0 = c_[4]; c1 = c_[5]; c2 = c_[6]; c3 = c_[7]; c4 = c_[8]; c5 = c_[9];
        e1_m = e1r[2]; e1_0 = e1r[3]; e1_1 = e1r[4]; e1_2 = e1r[5];
        e2_m = e2r[1]; e2_0 = e2r[2]; e2_1 = e2r[3];

        #pragma unroll 4
        for (int y = y0; y < y0 + SEGH; y++) {
            float2 c6 = *(const float2*)(cp + (y + 6) * W);
            float2 e1_3 = erode5p(c2, c3, c4);
            float2 e2_2 = erode5p(e1_1, e1_2, e1_3);
            float2 e3_1 = erode5p(e2_0, e2_1, e2_2);

            float2 openA = open3p(e2_m, e2_0, e2_1);
            float2 openB = open3p(e3_m, e3_0, e3_1);

            float2 s;
            if (MODE == 0) {
                float2 openI = open3p(e1_m, e1_0, e1_1);
                s.x = fmaxf(c0.x - openI.x, 0.0f);
                s.y = fmaxf(c0.y - openI.y, 0.0f);
            } else {
                s = *(const float2*)(skp + y * W);
            }
            float dA0 = fmaxf(e1_0.x - openA.x, 0.0f);
            float dA1 = fmaxf(e1_0.y - openA.y, 0.0f);
            s.x += fmaxf(dA0 - s.x * dA0, 0.0f);
            s.y += fmaxf(dA1 - s.y * dA1, 0.0f);
            float dB0 = fmaxf(e2_0.x - openB.x, 0.0f);
            float dB1 = fmaxf(e2_0.y - openB.y, 0.0f);
            s.x += fmaxf(dB0 - s.x * dB0, 0.0f);
            s.y += fmaxf(dB1 - s.y * dB1, 0.0f);

            if (MODE == 2) {
                if (laneOut) {
                    float2 t = *(const float2*)(pp + y * W);
                    float t0 = isPred ? fminf(fmaxf(t.x, 0.0f), 1.0f) : sigmoidf_(t.x);
                    float t1 = isPred ? fminf(fmaxf(t.y, 0.0f), 1.0f) : sigmoidf_(t.y);
                    float ps0 = fminf(fmaxf(s.x, 0.0f), 1.0f);
                    float ps1 = fminf(fmaxf(s.y, 0.0f), 1.0f);
                    accP += ps0 * t0 + ps1 * t1;
                    accS += ps0 + ps1;
                }
            } else if (laneOut) {
                *(float2*)(nxp + y * W) = e2_0;
                *(float2*)(skp + y * W) = s;
            }

            c0 = c1; c1 = c2; c2 = c3; c3 = c4; c4 = c5; c5 = c6;
            e1_m = e1_0; e1_0 = e1_1; e1_1 = e1_2; e1_2 = e1_3;
            e2_m = e2_0; e2_0 = e2_1; e2_1 = e2_2;
            e3_m = e3_0; e3_0 = e3_1;
        }
    } else {
        // ---------------- general (boundary) path ----------------
        float2 c_[10];
        #pragma unroll
        for (int i = 0; i < 10; i++) {
            int yy = y0 - 4 + i;
            bool rOK = (unsigned)yy < (unsigned)H;
            float2 v;
            v.x = (rOK && x0OK) ? cp[yy * W] : BIG;
            v.y = (rOK && x1OK) ? cp[yy * W + 1] : BIG;
            c_[i] = v;
        }
        float2 e1r[6];
        #pragma unroll
        for (int k = 0; k < 6; k++) {
            int r = y0 - 3 + k;
            e1r[k] = padv(erode5p(c_[k], c_[k + 1], c_[k + 2]),
                          (unsigned)r < (unsigned)H, x0OK, x1OK, BIG);
        }
        float2 e2r[4];   // raw
        #pragma unroll
        for (int k = 0; k < 4; k++) e2r[k] = erode5p(e1r[k], e1r[k + 1], e1r[k + 2]);

        float2 t0v = padv(e2r[0], (y0 - 2) >= 0, x0OK, x1OK, BIG);
        float2 t1v = padv(e2r[1], (y0 - 1) >= 0, x0OK, x1OK, BIG);
        float2 t2v = padv(e2r[2], true, x0OK, x1OK, BIG);
        float2 t3v = padv(e2r[3], true, x0OK, x1OK, BIG);
        e3_m = padv(erode5p(t0v, t1v, t2v), (y0 - 1) >= 0, x0OK, x1OK, -BIG);
        e3_0 = padv(erode5p(t1v, t2v, t3v), true, x0OK, x1OK, -BIG);

        c0 = c_[4]; c1 = c_[5]; c2 = c_[6]; c3 = c_[7]; c4 = c_[8]; c5 = c_[9];
        e1_m = e1r[2]; e1_0 = e1r[3]; e1_1 = e1r[4]; e1_2 = e1r[5];
        e2_m = e2r[1]; e2_0 = e2r[2]; e2_1 = e2r[3];

        #pragma unroll 4
        for (int y = y0; y < y0 + SEGH; y++) {
            int yl = y + 6;
            bool rl = (unsigned)yl < (unsigned)H;
            float2 c6;
            c6.x = (rl && x0OK) ? cp[yl * W] : BIG;
            c6.y = (rl && x1OK) ? cp[yl * W + 1] : BIG;

            float2 e1_3 = padv(erode5p(c2, c3, c4), (unsigned)(y + 3) < (unsigned)H, x0OK, x1OK, BIG);
            float2 e2_2 = erode5p(e1_1, e1_2, e1_3);

            float2 a = padv(e2_0, true, x0OK, x1OK, BIG);
            float2 b = padv(e2_1, (unsigned)(y + 1) < (unsigned)H, x0OK, x1OK, BIG);
            float2 d = padv(e2_2, (unsigned)(y + 2) < (unsigned)H, x0OK, x1OK, BIG);
            float2 e3_1 = padv(erode5p(a, b, d), (unsigned)(y + 1) < (unsigned)H, x0OK, x1OK, -BIG);

            float2 ma = padv(e2_m, (y - 1) >= 0, x0OK, x1OK, -BIG);
            float2 mb = padv(e2_0, true, x0OK, x1OK, -BIG);
            float2 mc = padv(e2_1, (unsigned)(y + 1) < (unsigned)H, x0OK, x1OK, -BIG);
            float2 openA = open3p(ma, mb, mc);
            float2 openB = open3p(e3_m, e3_0, e3_1);

            float2 s;
            if (MODE == 0) {
                float2 ia = padv(e1_m, (y - 1) >= 0, x0OK, x1OK, -BIG);
                float2 ib = padv(e1_0, true, x0OK, x1OK, -BIG);
                float2 ic = padv(e1_1, (unsigned)(y + 1) < (unsigned)H, x0OK, x1OK, -BIG);
                float2 openI = open3p(ia, ib, ic);
                s.x = fmaxf(c0.x - openI.x, 0.0f);
                s.y = fmaxf(c0.y - openI.y, 0.0f);
            } else {
                s.x = out0 ? skp[y * W] : 0.0f;
                s.y = out1 ? skp[y * W + 1] : 0.0f;
            }
            float dA0 = fmaxf(e1_0.x - openA.x, 0.0f);
            float dA1 = fmaxf(e1_0.y - openA.y, 0.0f);
            s.x += fmaxf(dA0 - s.x * dA0, 0.0f);
            s.y += fmaxf(dA1 - s.y * dA1, 0.0f);
            float dB0 = fmaxf(e2_0.x - openB.x, 0.0f);
            float dB1 = fmaxf(e2_0.y - openB.y, 0.0f);
            s.x += fmaxf(dB0 - s.x * dB0, 0.0f);
            s.y += fmaxf(dB1 - s.y * dB1, 0.0f);

            if (MODE == 2) {
                if (out0) {
                    float raw = pp[y * W];
                    float t = isPred ? fminf(fmaxf(raw, 0.0f), 1.0f) : sigmoidf_(raw);
                    float ps = fminf(fmaxf(s.x, 0.0f), 1.0f);
                    accP += ps * t;  accS += ps;
                }
                if (out1) {
                    float raw = pp[y * W + 1];
                    float t = isPred ? fminf(fmaxf(raw, 0.0f), 1.0f) : sigmoidf_(raw);
                    float ps = fminf(fmaxf(s.y, 0.0f), 1.0f);
                    accP += ps * t;  accS += ps;
                }
            } else {
                if (out0) { nxp[y * W] = e2_0.x;      skp[y * W] = s.x; }
                if (out1) { nxp[y * W + 1] = e2_0.y;  skp[y * W + 1] = s.y; }
            }

            c0 = c1; c1 = c2; c2 = c3; c3 = c4; c4 = c5; c5 = c6;
            e1_m = e1_0; e1_0 = e1_1; e1_1 = e1_2; e1_2 = e1_3;
            e2_m = e2_0; e2_0 = e2_1; e2_1 = e2_2;
            e3_m = e3_0; e3_0 = e3_1;
        }
    }

    if (MODE == 2) {
        #pragma unroll
        for (int o = 16; o > 0; o >>= 1) {
            accP += __shfl_down_sync(0xffffffffu, accP, o);
            accS += __shfl_down_sync(0xffffffffu, accS, o);
        }
        if (lane == 0) {
            int idx = 54 + b8 * 4 + (isPred ? 0 : 2);
            atomicAdd(&g_acc[idx], accP);
            atomicAdd(&g_acc[idx + 1], accS);
        }
    }
}

// ---------------------------------------------------------------------------
__global__ void finalize_kernel(float* __restrict__ out) {
    const float N = (float)NELEM;
    float dice_m = 0.f, dice_s = 0.f, cl = 0.f;
    #pragma unroll
    for (int b = 0; b < NB; b++) {
        float im = g_acc[b * 6 + 0], pm = g_acc[b * 6 + 1], tm = g_acc[b * 6 + 2];
        dice_m += (2.0f * im + EPSF) / (pm + tm + EPSF);
        float is = g_acc[b * 6 + 3], ps = g_acc[b * 6 + 4], ts = g_acc[b * 6 + 5];
        dice_s += (2.0f * is + EPSF) / (ps + ts + EPSF);
        float c0 = g_acc[54 + b * 4 + 0], c1 = g_acc[54 + b * 4 + 1];
        float c2 = g_acc[54 + b * 4 + 2], c3 = g_acc[54 + b * 4 + 3];
        float prec = c0 / (c1 + EPSF);
        float sens = c2 / (c3 + EPSF);
        cl += (2.0f * prec * sens + EPSF) / (prec + sens + EPSF);
    }
    dice_m *= 0.125f;  dice_s *= 0.125f;  cl *= 0.125f;

    float mask_loss     = (1.0f - dice_m) + g_acc[48] / N;
    float skeleton_loss = 1.0f - dice_s;
    float topology_loss = 1.0f - cl;
    float node_loss     = 0.5f * (g_acc[49] / N + g_acc[50] / N);
    float msum          = g_acc[52];
    float aff_loss      = (msum == 0.0f) ? 0.0f : g_acc[51] / fmaxf(msum, 1.0f);
    float unc_loss      = g_acc[53] / N;

    out[0] = 1.0f * mask_loss + 1.0f * skeleton_loss + 0.5f * topology_loss +
             0.5f * node_loss + 0.5f * aff_loss + 0.1f * unc_loss;
}

// ---------------------------------------------------------------------------
extern "C" void kernel_launch(void* const* d_in, const int* in_sizes, int n_in,
                              void* d_out, int out_size) {
    const float* ml = (const float*)d_in[0];
    const float* mk = (const float*)d_in[6];
    float* out = (float*)d_out;

    zero_acc_kernel<<<1, 96>>>();

    dim3 gA(64, NB);
    pass_a_kernel<<<gA, 256>>>(
        (const float4*)d_in[0], (const float4*)d_in[1], (const float4*)d_in[2],
        (const float4*)d_in[3], (const float4*)d_in[4], (const float4*)d_in[5],
        (const float4*)d_in[6], (const float4*)d_in[7], (const float4*)d_in[8],
        (const float4*)d_in[9], (const float4*)d_in[10], (const float4*)d_in[11]);

    // iters 1,2 (init)  A -> B
    skel2_kernel<0><<<GRIDP, 64>>>(1, ml, mk);
    // iters 3,4  B -> A ; 5,6  A -> B ; 7,8  B -> A
    skel2_kernel<1><<<GRIDP, 64>>>(0, ml, mk);
    skel2_kernel<1><<<GRIDP, 64>>>(1, ml, mk);
    skel2_kernel<1><<<GRIDP, 64>>>(0, ml, mk);
    // iters 9,10 + clDice reduce, read A, no writes
    skel2_kernel<2><<<GRIDP, 64>>>(1, ml, mk);

    finalize_kernel<<<1, 1>>>(out);
}

// round 11
// speedup vs baseline: 1.2265x; 1.0415x over previous
#include <cuda_runtime.h>
#include <math.h>

#define H 512
#define W 512
#define PLANE (H*W)
#define NB 8
#define NPL 16
#define NELEM (NB*PLANE)
#define EPSF 1e-6f
#define BIG 1e30f

// 2-col-per-thread skeletonize layout: 56 useful cols per warp, 16 rows per seg
#define STRIPSP 10
#define SEGSP   32
#define SEGH    16
#define BLK_WARPS 4
#define WARPSP (NPL*STRIPSP*SEGSP)      // 5120
#define GRIDP  (WARPSP/BLK_WARPS)       // 1280

__device__ float g_bufA[NPL*PLANE];
__device__ float g_bufB[NPL*PLANE];
__device__ float g_skel[NPL*PLANE];
__device__ float g_acc[96];

// fast sigmoid: sigmoid(x) = 0.5*tanh(x/2) + 0.5  (MUFU.TANH, sm_75+)
__device__ __forceinline__ float sigmoidf_(float x) {
    float t;
    asm("tanh.approx.f32 %0, %1;" : "=f"(t) : "f"(0.5f * x));
    return fmaf(0.5f, t, 0.5f);
}

__device__ __forceinline__ float focal_elem(float x, float t) {
    // bce = max(x,0) - x*t + log(1 + exp(-|x|))
    float e = __expf(-fabsf(x));
    float bce = fmaxf(x, 0.0f) - x * t + __logf(1.0f + e);
    float p   = sigmoidf_(x);
    float pt  = p * t + (1.0f - p) * (1.0f - t);
    float at  = 0.25f * t + 0.75f * (1.0f - t);
    float om  = 1.0f - pt;
    return at * om * om * bce;
}

__device__ __forceinline__ float blk_sum(float v, float* sh) {
    int tid = threadIdx.x;
    #pragma unroll
    for (int o = 16; o > 0; o >>= 1) v += __shfl_down_sync(0xffffffffu, v, o);
    if ((tid & 31) == 0) sh[tid >> 5] = v;
    __syncthreads();
    float r = 0.0f;
    if (tid < 32) {
        r = (tid < (int)(blockDim.x >> 5)) ? sh[tid] : 0.0f;
        #pragma unroll
        for (int o = 16; o > 0; o >>= 1) r += __shfl_down_sync(0xffffffffu, r, o);
    }
    __syncthreads();
    return r;
}

// pairwise 5-pt cross erode over 64 warp columns (cols x0=2*lane, x1=2*lane+1)
__device__ __forceinline__ float2 erode5p(float2 m, float2 c, float2 p) {
    float lm = __shfl_up_sync(0xffffffffu, c.y, 1);
    float rm = __shfl_down_sync(0xffffffffu, c.x, 1);
    float2 r;
    r.x = fminf(fminf(fminf(m.x, p.x), c.x), fminf(lm, c.y));
    r.y = fminf(fminf(fminf(m.y, p.y), c.y), fminf(c.x, rm));
    return r;
}
// pairwise 3x3 max (open)
__device__ __forceinline__ float2 open3p(float2 m, float2 c, float2 p) {
    float2 v;
    v.x = fmaxf(fmaxf(m.x, p.x), c.x);
    v.y = fmaxf(fmaxf(m.y, p.y), c.y);
    float lm = __shfl_up_sync(0xffffffffu, v.y, 1);
    float rm = __shfl_down_sync(0xffffffffu, v.x, 1);
    float2 r;
    r.x = fmaxf(v.x, fmaxf(lm, v.y));
    r.y = fmaxf(v.y, fmaxf(v.x, rm));
    return r;
}
__device__ __forceinline__ float2 padv(float2 v, bool rowOK, bool x0OK, bool x1OK, float pad) {
    float2 r;
    r.x = (rowOK && x0OK) ? v.x : pad;
    r.y = (rowOK && x1OK) ? v.y : pad;
    return r;
}

__global__ void zero_acc_kernel() {
    if (threadIdx.x < 96) g_acc[threadIdx.x] = 0.0f;
}

// ---------------------------------------------------------------------------
// Pass A (float4-vectorized); seeds g_bufA only.
// ---------------------------------------------------------------------------
__global__ void pass_a_kernel(const float4* __restrict__ ml, const float4* __restrict__ sl,
                              const float4* __restrict__ ul, const float4* __restrict__ jl,
                              const float4* __restrict__ el, const float4* __restrict__ ap,
                              const float4* __restrict__ mk, const float4* __restrict__ sk,
                              const float4* __restrict__ jn, const float4* __restrict__ ep,
                              const float4* __restrict__ at, const float4* __restrict__ un) {
    const int Q = PLANE / 4;
    int b   = blockIdx.y;
    int tid = threadIdx.x;
    int base = b * Q;

    float4* __restrict__ bufap = (float4*)g_bufA;

    float di = 0.f, dp = 0.f, dt = 0.f;
    float si = 0.f, spp = 0.f, stt = 0.f;
    float fm = 0.f, fj = 0.f, fe = 0.f;
    float sl1 = 0.f, msum = 0.f, usum = 0.f;

    for (int i = blockIdx.x * blockDim.x + tid; i < Q; i += gridDim.x * blockDim.x) {
        int g = base + i;
        float4 xm4 = ml[g];
        float4 tm4 = mk[g];
        float4 pm4, tmc4;

        #pragma unroll
        for (int u = 0; u < 4; u++) {
            float xm = ((float*)&xm4)[u];
            float tm = ((float*)&tm4)[u];
            float pm = sigmoidf_(xm);
            ((float*)&pm4)[u] = pm;
            ((float*)&tmc4)[u] = fminf(fmaxf(tm, 0.0f), 1.0f);
            di += pm * tm;  dp += pm;  dt += tm;
            fm += focal_elem(xm, tm);
        }
        bufap[g] = pm4;
        bufap[(8 + b) * Q + i] = tmc4;

        float4 ts4 = sk[g];
        float4 ps4 = sl[g];
        float4 jl4 = jl[g], jn4 = jn[g], el4 = el[g], ep4 = ep[g];
        float4 ul4 = ul[g], un4 = un[g];
        float4 ap0 = ap[b * 2 * Q + i], ap1 = ap[b * 2 * Q + Q + i];
        float4 at0 = at[b * 2 * Q + i], at1 = at[b * 2 * Q + Q + i];

        #pragma unroll
        for (int u = 0; u < 4; u++) {
            float ts = ((float*)&ts4)[u];
            float psk = sigmoidf_(((float*)&ps4)[u]);
            si += psk * ts;  spp += psk;  stt += ts;

            fj += focal_elem(((float*)&jl4)[u], ((float*)&jn4)[u]);
            fe += focal_elem(((float*)&el4)[u], ((float*)&ep4)[u]);

            float pu = sigmoidf_(((float*)&ul4)[u]);
            float du = pu - ((float*)&un4)[u];
            usum += du * du;

            float m = ts;
            float d0 = ((float*)&ap0)[u] * m - ((float*)&at0)[u] * m;
            float ad0 = fabsf(d0);
            sl1 += (ad0 < 1.0f) ? 0.5f * d0 * d0 : ad0 - 0.5f;
            float d1 = ((float*)&ap1)[u] * m - ((float*)&at1)[u] * m;
            float ad1 = fabsf(d1);
            sl1 += (ad1 < 1.0f) ? 0.5f * d1 * d1 : ad1 - 0.5f;
            msum += 2.0f * m;
        }
    }

    __shared__ float sh[32];
    float vals[12] = {di, dp, dt, si, spp, stt, fm, fj, fe, sl1, msum, usum};
    #pragma unroll
    for (int k = 0; k < 12; k++) {
        float r = blk_sum(vals[k], sh);
        if (tid == 0) {
            int a = (k < 6) ? (b * 6 + k) : (42 + k);
            atomicAdd(&g_acc[a], r);
        }
    }
}

// ---------------------------------------------------------------------------
// Fused double-iteration skeletonize, 2 columns per thread.
//  MODE 0: init + iters 1,2  (skel pure write)
//  MODE 1: two iterations     (skel RMW)
//  MODE 2: final two iters + clDice accumulation (no global writes)
//  MINB:   min blocks per SM for launch_bounds (reg cap)
// ---------------------------------------------------------------------------
template<int MODE, int MINB>
__global__ void __launch_bounds__(128, MINB) skel2_kernel(int useA,
                                                          const float* __restrict__ ml,
                                                          const float* __restrict__ mk) {
    const float* __restrict__ cur = useA ? g_bufA : g_bufB;
    float* __restrict__ nxt = useA ? g_bufB : g_bufA;

    int lane = threadIdx.x & 31;
    int wg = blockIdx.x * BLK_WARPS + (threadIdx.x >> 5);
    int plane = wg / (STRIPSP * SEGSP);
    int rem = wg - plane * (STRIPSP * SEGSP);
    int strip = rem / SEGSP;
    int seg = rem & (SEGSP - 1);

    int x0 = strip * 56 - 4 + 2 * lane;       // even
    int x1 = x0 + 1;
    bool x0OK = (unsigned)x0 < (unsigned)W;
    bool x1OK = (unsigned)x1 < (unsigned)W;
    bool laneOut = (lane >= 2) && (lane <= 29);
    bool out0 = laneOut && x0OK;
    bool out1 = laneOut && x1OK;
    int y0 = seg * SEGH;
    int base = plane * PLANE;

    const float* __restrict__ cp = cur + base + x0;
    float* __restrict__ skp = g_skel + base + x0;
    float* __restrict__ nxp = nxt + base + x0;

    // clDice partner source (MODE 2): plane<8 -> clip(mask), plane>=8 -> sigmoid(mask_logits)
    bool isPred = (plane < 8);
    int b8 = isPred ? plane : (plane - 8);
    const float* __restrict__ pp = (isPred ? mk : ml) + b8 * PLANE + x0;
    float accP = 0.0f, accS = 0.0f;

    bool fast = (strip >= 1) && (strip <= 8) && (seg >= 1) && (seg <= 30);

    float2 c0, c1, c2, c3, c4, c5;
    float2 e1_m, e1_0, e1_1, e1_2;
    float2 e2_m, e2_0, e2_1;
    float2 e3_m, e3_0;

    if (fast) {
        float2 c_[10];
        #pragma unroll
        for (int i = 0; i < 10; i++) c_[i] = *(const float2*)(cp + (y0 - 4 + i) * W);
        float2 e1r[6];
        #pragma unroll
        for (int k = 0; k < 6; k++) e1r[k] = erode5p(c_[k], c_[k + 1], c_[k + 2]);
        float2 e2r[4];
        #pragma unroll
        for (int k = 0; k < 4; k++) e2r[k] = erode5p(e1r[k], e1r[k + 1], e1r[k + 2]);
        e3_m = erode5p(e2r[0], e2r[1], e2r[2]);
        e3_0 = erode5p(e2r[1], e2r[2], e2r[3]);

        c0 = c_[4]; c1 = c_[5]; c2 = c_[6]; c3 = c_[7]; c4 = c_[8]; c5 = c_[9];
        e1_m = e1r[2]; e1_0 = e1r[3]; e1_1 = e1r[4]; e1_2 = e1r[5];
        e2_m = e2r[1]; e2_0 = e2r[2]; e2_1 = e2r[3];

        #pragma unroll 4
        for (int y = y0; y < y0 + SEGH; y++) {
            float2 c6 = *(const float2*)(cp + (y + 6) * W);
            float2 e1_3 = erode5p(c2, c3, c4);
            float2 e2_2 = erode5p(e1_1, e1_2, e1_3);
            float2 e3_1 = erode5p(e2_0, e2_1, e2_2);

            float2 openA = open3p(e2_m, e2_0, e2_1);
            float2 openB = open3p(e3_m, e3_0, e3_1);

            float2 s;
            if (MODE == 0) {
                float2 openI = open3p(e1_m, e1_0, e1_1);
                s.x = fmaxf(c0.x - openI.x, 0.0f);
                s.y = fmaxf(c0.y - openI.y, 0.0f);
            } else {
                s = *(const float2*)(skp + y * W);
            }
            float dA0 = fmaxf(e1_0.x - openA.x, 0.0f);
            float dA1 = fmaxf(e1_0.y - openA.y, 0.0f);
            s.x += fmaxf(dA0 - s.x * dA0, 0.0f);
            s.y += fmaxf(dA1 - s.y * dA1, 0.0f);
            float dB0 = fmaxf(e2_0.x - openB.x, 0.0f);
            float dB1 = fmaxf(e2_0.y - openB.y, 0.0f);
            s.x += fmaxf(dB0 - s.x * dB0, 0.0f);
            s.y += fmaxf(dB1 - s.y * dB1, 0.0f);

            if (MODE == 2) {
                if (laneOut) {
                    float2 t = *(const float2*)(pp + y * W);
                    float t0 = isPred ? fminf(fmaxf(t.x, 0.0f), 1.0f) : sigmoidf_(t.x);
                    float t1 = isPred ? fminf(fmaxf(t.y, 0.0f), 1.0f) : sigmoidf_(t.y);
                    float ps0 = fminf(fmaxf(s.x, 0.0f), 1.0f);
                    float ps1 = fminf(fmaxf(s.y, 0.0f), 1.0f);
                    accP += ps0 * t0 + ps1 * t1;
                    accS += ps0 + ps1;
                }
            } else if (laneOut) {
                *(float2*)(nxp + y * W) = e2_0;
                *(float2*)(skp + y * W) = s;
            }

            if (MODE == 0) { c0 = c1; c1 = c2; }
            c2 = c3; c3 = c4; c4 = c5; c5 = c6;
            if (MODE == 0) e1_m = e1_0;
            e1_0 = e1_1; e1_1 = e1_2; e1_2 = e1_3;
            e2_m = e2_0; e2_0 = e2_1; e2_1 = e2_2;
            e3_m = e3_0; e3_0 = e3_1;
        }
    } else {
        // ---------------- general (boundary) path ----------------
        float2 c_[10];
        #pragma unroll
        for (int i = 0; i < 10; i++) {
            int yy = y0 - 4 + i;
            bool rOK = (unsigned)yy < (unsigned)H;
            float2 v;
            v.x = (rOK && x0OK) ? cp[yy * W] : BIG;
            v.y = (rOK && x1OK) ? cp[yy * W + 1] : BIG;
            c_[i] = v;
        }
        float2 e1r[6];
        #pragma unroll
        for (int k = 0; k < 6; k++) {
            int r = y0 - 3 + k;
            e1r[k] = padv(erode5p(c_[k], c_[k + 1], c_[k + 2]),
                          (unsigned)r < (unsigned)H, x0OK, x1OK, BIG);
        }
        float2 e2r[4];   // raw
        #pragma unroll
        for (int k = 0; k < 4; k++) e2r[k] = erode5p(e1r[k], e1r[k + 1], e1r[k + 2]);

        float2 t0v = padv(e2r[0], (y0 - 2) >= 0, x0OK, x1OK, BIG);
        float2 t1v = padv(e2r[1], (y0 - 1) >= 0, x0OK, x1OK, BIG);
        float2 t2v = padv(e2r[2], true, x0OK, x1OK, BIG);
        float2 t3v = padv(e2r[3], true, x0OK, x1OK, BIG);
        e3_m = padv(erode5p(t0v, t1v, t2v), (y0 - 1) >= 0, x0OK, x1OK, -BIG);
        e3_0 = padv(erode5p(t1v, t2v, t3v), true, x0OK, x1OK, -BIG);

        c0 = c_[4]; c1 = c_[5]; c2 = c_[6]; c3 = c_[7]; c4 = c_[8]; c5 = c_[9];
        e1_m = e1r[2]; e1_0 = e1r[3]; e1_1 = e1r[4]; e1_2 = e1r[5];
        e2_m = e2r[1]; e2_0 = e2r[2]; e2_1 = e2r[3];

        #pragma unroll 4
        for (int y = y0; y < y0 + SEGH; y++) {
            int yl = y + 6;
            bool rl = (unsigned)yl < (unsigned)H;
            float2 c6;
            c6.x = (rl && x0OK) ? cp[yl * W] : BIG;
            c6.y = (rl && x1OK) ? cp[yl * W + 1] : BIG;

            float2 e1_3 = padv(erode5p(c2, c3, c4), (unsigned)(y + 3) < (unsigned)H, x0OK, x1OK, BIG);
            float2 e2_2 = erode5p(e1_1, e1_2, e1_3);

            float2 a = padv(e2_0, true, x0OK, x1OK, BIG);
            float2 b = padv(e2_1, (unsigned)(y + 1) < (unsigned)H, x0OK, x1OK, BIG);
            float2 d = padv(e2_2, (unsigned)(y + 2) < (unsigned)H, x0OK, x1OK, BIG);
            float2 e3_1 = padv(erode5p(a, b, d), (unsigned)(y + 1) < (unsigned)H, x0OK, x1OK, -BIG);

            float2 ma = padv(e2_m, (y - 1) >= 0, x0OK, x1OK, -BIG);
            float2 mb = padv(e2_0, true, x0OK, x1OK, -BIG);
            float2 mc = padv(e2_1, (unsigned)(y + 1) < (unsigned)H, x0OK, x1OK, -BIG);
            float2 openA = open3p(ma, mb, mc);
            float2 openB = open3p(e3_m, e3_0, e3_1);

            float2 s;
            if (MODE == 0) {
                float2 ia = padv(e1_m, (y - 1) >= 0, x0OK, x1OK, -BIG);
                float2 ib = padv(e1_0, true, x0OK, x1OK, -BIG);
                float2 ic = padv(e1_1, (unsigned)(y + 1) < (unsigned)H, x0OK, x1OK, -BIG);
                float2 openI = open3p(ia, ib, ic);
                s.x = fmaxf(c0.x - openI.x, 0.0f);
                s.y = fmaxf(c0.y - openI.y, 0.0f);
            } else {
                s.x = out0 ? skp[y * W] : 0.0f;
                s.y = out1 ? skp[y * W + 1] : 0.0f;
            }
            float dA0 = fmaxf(e1_0.x - openA.x, 0.0f);
            float dA1 = fmaxf(e1_0.y - openA.y, 0.0f);
            s.x += fmaxf(dA0 - s.x * dA0, 0.0f);
            s.y += fmaxf(dA1 - s.y * dA1, 0.0f);
            float dB0 = fmaxf(e2_0.x - openB.x, 0.0f);
            float dB1 = fmaxf(e2_0.y - openB.y, 0.0f);
            s.x += fmaxf(dB0 - s.x * dB0, 0.0f);
            s.y += fmaxf(dB1 - s.y * dB1, 0.0f);

            if (MODE == 2) {
                if (out0) {
                    float raw = pp[y * W];
                    float t = isPred ? fminf(fmaxf(raw, 0.0f), 1.0f) : sigmoidf_(raw);
                    float ps = fminf(fmaxf(s.x, 0.0f), 1.0f);
                    accP += ps * t;  accS += ps;
                }
                if (out1) {
                    float raw = pp[y * W + 1];
                    float t = isPred ? fminf(fmaxf(raw, 0.0f), 1.0f) : sigmoidf_(raw);
                    float ps = fminf(fmaxf(s.y, 0.0f), 1.0f);
                    accP += ps * t;  accS += ps;
                }
            } else {
                if (out0) { nxp[y * W] = e2_0.x;      skp[y * W] = s.x; }
                if (out1) { nxp[y * W + 1] = e2_0.y;  skp[y * W + 1] = s.y; }
            }

            c0 = c1; c1 = c2; c2 = c3; c3 = c4; c4 = c5; c5 = c6;
            e1_m = e1_0; e1_0 = e1_1; e1_1 = e1_2; e1_2 = e1_3;
            e2_m = e2_0; e2_0 = e2_1; e2_1 = e2_2;
            e3_m = e3_0; e3_0 = e3_1;
        }
    }

    if (MODE == 2) {
        #pragma unroll
        for (int o = 16; o > 0; o >>= 1) {
            accP += __shfl_down_sync(0xffffffffu, accP, o);
            accS += __shfl_down_sync(0xffffffffu, accS, o);
        }
        if (lane == 0) {
            int idx = 54 + b8 * 4 + (isPred ? 0 : 2);
            atomicAdd(&g_acc[idx], accP);
            atomicAdd(&g_acc[idx + 1], accS);
        }
    }
}

// ---------------------------------------------------------------------------
__global__ void finalize_kernel(float* __restrict__ out) {
    const float N = (float)NELEM;
    float dice_m = 0.f, dice_s = 0.f, cl = 0.f;
    #pragma unroll
    for (int b = 0; b < NB; b++) {
        float im = g_acc[b * 6 + 0], pm = g_acc[b * 6 + 1], tm = g_acc[b * 6 + 2];
        dice_m += (2.0f * im + EPSF) / (pm + tm + EPSF);
        float is = g_acc[b * 6 + 3], ps = g_acc[b * 6 + 4], ts = g_acc[b * 6 + 5];
        dice_s += (2.0f * is + EPSF) / (ps + ts + EPSF);
        float c0 = g_acc[54 + b * 4 + 0], c1 = g_acc[54 + b * 4 + 1];
        float c2 = g_acc[54 + b * 4 + 2], c3 = g_acc[54 + b * 4 + 3];
        float prec = c0 / (c1 + EPSF);
        float sens = c2 / (c3 + EPSF);
        cl += (2.0f * prec * sens + EPSF) / (prec + sens + EPSF);
    }
    dice_m *= 0.125f;  dice_s *= 0.125f;  cl *= 0.125f;

    float mask_loss     = (1.0f - dice_m) + g_acc[48] / N;
    float skeleton_loss = 1.0f - dice_s;
    float topology_loss = 1.0f - cl;
    float node_loss     = 0.5f * (g_acc[49] / N + g_acc[50] / N);
    float msum          = g_acc[52];
    float aff_loss      = (msum == 0.0f) ? 0.0f : g_acc[51] / fmaxf(msum, 1.0f);
    float unc_loss      = g_acc[53] / N;

    out[0] = 1.0f * mask_loss + 1.0f * skeleton_loss + 0.5f * topology_loss +
             0.5f * node_loss + 0.5f * aff_loss + 0.1f * unc_loss;
}

// ---------------------------------------------------------------------------
extern "C" void kernel_launch(void* const* d_in, const int* in_sizes, int n_in,
                              void* d_out, int out_size) {
    const float* ml = (const float*)d_in[0];
    const float* mk = (const float*)d_in[6];
    float* out = (float*)d_out;

    zero_acc_kernel<<<1, 96>>>();

    dim3 gA(64, NB);
    pass_a_kernel<<<gA, 256>>>(
        (const float4*)d_in[0], (const float4*)d_in[1], (const float4*)d_in[2],
        (const float4*)d_in[3], (const float4*)d_in[4], (const float4*)d_in[5],
        (const float4*)d_in[6], (const float4*)d_in[7], (const float4*)d_in[8],
        (const float4*)d_in[9], (const float4*)d_in[10], (const float4*)d_in[11]);

    // iters 1,2 (init)  A -> B
    skel2_kernel<0, 9><<<GRIDP, 128>>>(1, ml, mk);
    // iters 3,4  B -> A ; 5,6  A -> B ; 7,8  B -> A   (reg-capped for occupancy)
    skel2_kernel<1, 10><<<GRIDP, 128>>>(0, ml, mk);
    skel2_kernel<1, 10><<<GRIDP, 128>>>(1, ml, mk);
    skel2_kernel<1, 10><<<GRIDP, 128>>>(0, ml, mk);
    // iters 9,10 + clDice reduce, read A, no writes
    skel2_kernel<2, 9><<<GRIDP, 128>>>(1, ml, mk);

    finalize_kernel<<<1, 1>>>(out);
}

// round 12
// speedup vs baseline: 1.3171x; 1.0739x over previous
#include <cuda_runtime.h>
#include <math.h>

#define H 512
#define W 512
#define PLANE (H*W)
#define NB 8
#define NPL 16
#define NELEM (NB*PLANE)
#define EPSF 1e-6f
#define BIG 1e30f

// 2-col-per-thread skeletonize layout: 56 useful cols per warp, 16 rows per seg
#define STRIPSP 10
#define SEGSP   32
#define SEGH    16
#define BLK_WARPS 4
#define WARPSP (NPL*STRIPSP*SEGSP)      // 5120
#define GRIDP  (WARPSP/BLK_WARPS)       // 1280

__device__ float g_bufA[NPL*PLANE];
__device__ float g_bufB[NPL*PLANE];
__device__ float g_skel[NPL*PLANE];
__device__ float g_acc[96];

// fast sigmoid: sigmoid(x) = 0.5*tanh(x/2) + 0.5  (MUFU.TANH, sm_75+)
__device__ __forceinline__ float sigmoidf_(float x) {
    float t;
    asm("tanh.approx.f32 %0, %1;" : "=f"(t) : "f"(0.5f * x));
    return fmaf(0.5f, t, 0.5f);
}

__device__ __forceinline__ float focal_elem(float x, float t) {
    // bce = max(x,0) - x*t + log(1 + exp(-|x|))
    float e = __expf(-fabsf(x));
    float bce = fmaxf(x, 0.0f) - x * t + __logf(1.0f + e);
    float p   = sigmoidf_(x);
    float pt  = p * t + (1.0f - p) * (1.0f - t);
    float at  = 0.25f * t + 0.75f * (1.0f - t);
    float om  = 1.0f - pt;
    return at * om * om * bce;
}

__device__ __forceinline__ float blk_sum(float v, float* sh) {
    int tid = threadIdx.x;
    #pragma unroll
    for (int o = 16; o > 0; o >>= 1) v += __shfl_down_sync(0xffffffffu, v, o);
    if ((tid & 31) == 0) sh[tid >> 5] = v;
    __syncthreads();
    float r = 0.0f;
    if (tid < 32) {
        r = (tid < (int)(blockDim.x >> 5)) ? sh[tid] : 0.0f;
        #pragma unroll
        for (int o = 16; o > 0; o >>= 1) r += __shfl_down_sync(0xffffffffu, r, o);
    }
    __syncthreads();
    return r;
}

// pairwise 5-pt cross erode over 64 warp columns (cols x0=2*lane, x1=2*lane+1)
__device__ __forceinline__ float2 erode5p(float2 m, float2 c, float2 p) {
    float lm = __shfl_up_sync(0xffffffffu, c.y, 1);
    float rm = __shfl_down_sync(0xffffffffu, c.x, 1);
    float2 r;
    r.x = fminf(fminf(fminf(m.x, p.x), c.x), fminf(lm, c.y));
    r.y = fminf(fminf(fminf(m.y, p.y), c.y), fminf(c.x, rm));
    return r;
}
// pairwise 3x3 max (open)
__device__ __forceinline__ float2 open3p(float2 m, float2 c, float2 p) {
    float2 v;
    v.x = fmaxf(fmaxf(m.x, p.x), c.x);
    v.y = fmaxf(fmaxf(m.y, p.y), c.y);
    float lm = __shfl_up_sync(0xffffffffu, v.y, 1);
    float rm = __shfl_down_sync(0xffffffffu, v.x, 1);
    float2 r;
    r.x = fmaxf(v.x, fmaxf(lm, v.y));
    r.y = fmaxf(v.y, fmaxf(v.x, rm));
    return r;
}
__device__ __forceinline__ float2 padv(float2 v, bool rowOK, bool x0OK, bool x1OK, float pad) {
    float2 r;
    r.x = (rowOK && x0OK) ? v.x : pad;
    r.y = (rowOK && x1OK) ? v.y : pad;
    return r;
}

__global__ void zero_acc_kernel() {
    if (threadIdx.x < 96) g_acc[threadIdx.x] = 0.0f;
}

// ---------------------------------------------------------------------------
// Pass A (float4-vectorized); seeds g_bufA only.
// ---------------------------------------------------------------------------
__global__ void pass_a_kernel(const float4* __restrict__ ml, const float4* __restrict__ sl,
                              const float4* __restrict__ ul, const float4* __restrict__ jl,
                              const float4* __restrict__ el, const float4* __restrict__ ap,
                              const float4* __restrict__ mk, const float4* __restrict__ sk,
                              const float4* __restrict__ jn, const float4* __restrict__ ep,
                              const float4* __restrict__ at, const float4* __restrict__ un) {
    const int Q = PLANE / 4;
    int b   = blockIdx.y;
    int tid = threadIdx.x;
    int base = b * Q;

    float4* __restrict__ bufap = (float4*)g_bufA;

    float di = 0.f, dp = 0.f, dt = 0.f;
    float si = 0.f, spp = 0.f, stt = 0.f;
    float fm = 0.f, fj = 0.f, fe = 0.f;
    float sl1 = 0.f, msum = 0.f, usum = 0.f;

    for (int i = blockIdx.x * blockDim.x + tid; i < Q; i += gridDim.x * blockDim.x) {
        int g = base + i;
        float4 xm4 = ml[g];
        float4 tm4 = mk[g];
        float4 pm4, tmc4;

        #pragma unroll
        for (int u = 0; u < 4; u++) {
            float xm = ((float*)&xm4)[u];
            float tm = ((float*)&tm4)[u];
            float pm = sigmoidf_(xm);
            ((float*)&pm4)[u] = pm;
            ((float*)&tmc4)[u] = fminf(fmaxf(tm, 0.0f), 1.0f);
            di += pm * tm;  dp += pm;  dt += tm;
            fm += focal_elem(xm, tm);
        }
        bufap[g] = pm4;
        bufap[(8 + b) * Q + i] = tmc4;

        float4 ts4 = sk[g];
        float4 ps4 = sl[g];
        float4 jl4 = jl[g], jn4 = jn[g], el4 = el[g], ep4 = ep[g];
        float4 ul4 = ul[g], un4 = un[g];
        float4 ap0 = ap[b * 2 * Q + i], ap1 = ap[b * 2 * Q + Q + i];
        float4 at0 = at[b * 2 * Q + i], at1 = at[b * 2 * Q + Q + i];

        #pragma unroll
        for (int u = 0; u < 4; u++) {
            float ts = ((float*)&ts4)[u];
            float psk = sigmoidf_(((float*)&ps4)[u]);
            si += psk * ts;  spp += psk;  stt += ts;

            fj += focal_elem(((float*)&jl4)[u], ((float*)&jn4)[u]);
            fe += focal_elem(((float*)&el4)[u], ((float*)&ep4)[u]);

            float pu = sigmoidf_(((float*)&ul4)[u]);
            float du = pu - ((float*)&un4)[u];
            usum += du * du;

            float m = ts;
            float d0 = ((float*)&ap0)[u] * m - ((float*)&at0)[u] * m;
            float ad0 = fabsf(d0);
            sl1 += (ad0 < 1.0f) ? 0.5f * d0 * d0 : ad0 - 0.5f;
            float d1 = ((float*)&ap1)[u] * m - ((float*)&at1)[u] * m;
            float ad1 = fabsf(d1);
            sl1 += (ad1 < 1.0f) ? 0.5f * d1 * d1 : ad1 - 0.5f;
            msum += 2.0f * m;
        }
    }

    __shared__ float sh[32];
    float vals[12] = {di, dp, dt, si, spp, stt, fm, fj, fe, sl1, msum, usum};
    #pragma unroll
    for (int k = 0; k < 12; k++) {
        float r = blk_sum(vals[k], sh);
        if (tid == 0) {
            int a = (k < 6) ? (b * 6 + k) : (42 + k);
            atomicAdd(&g_acc[a], r);
        }
    }
}

// ---------------------------------------------------------------------------
// Fused double-iteration skeletonize, 2 columns per thread.
//  MODE 0: init + iters 1,2  (skel pure write)
//  MODE 1: two iterations     (skel RMW)
//  MODE 2: final two iters + clDice accumulation (no global writes)
// ---------------------------------------------------------------------------
template<int MODE>
__global__ void __launch_bounds__(128, 9) skel2_kernel(int useA,
                                                       const float* __restrict__ ml,
                                                       const float* __restrict__ mk) {
    const float* __restrict__ cur = useA ? g_bufA : g_bufB;
    float* __restrict__ nxt = useA ? g_bufB : g_bufA;

    int lane = threadIdx.x & 31;
    int wg = blockIdx.x * BLK_WARPS + (threadIdx.x >> 5);
    int plane = wg / (STRIPSP * SEGSP);
    int rem = wg - plane * (STRIPSP * SEGSP);
    int strip = rem / SEGSP;
    int seg = rem & (SEGSP - 1);

    int x0 = strip * 56 - 4 + 2 * lane;       // even
    int x1 = x0 + 1;
    bool x0OK = (unsigned)x0 < (unsigned)W;
    bool x1OK = (unsigned)x1 < (unsigned)W;
    bool laneOut = (lane >= 2) && (lane <= 29);
    bool out0 = laneOut && x0OK;
    bool out1 = laneOut && x1OK;
    int y0 = seg * SEGH;
    int base = plane * PLANE;

    const float* __restrict__ cp = cur + base + x0;
    float* __restrict__ skp = g_skel + base + x0;
    float* __restrict__ nxp = nxt + base + x0;

    // clDice partner source (MODE 2): plane<8 -> clip(mask), plane>=8 -> sigmoid(mask_logits)
    bool isPred = (plane < 8);
    int b8 = isPred ? plane : (plane - 8);
    const float* __restrict__ pp = (isPred ? mk : ml) + b8 * PLANE + x0;
    float accP = 0.0f, accS = 0.0f;

    bool fast = (strip >= 1) && (strip <= 8) && (seg >= 1) && (seg <= 30);

    float2 c0, c1, c2, c3, c4, c5;
    float2 e1_m, e1_0, e1_1, e1_2;
    float2 e2_m, e2_0, e2_1;
    float2 e3_m, e3_0;

    if (fast) {
        float2 c_[10];
        #pragma unroll
        for (int i = 0; i < 10; i++) c_[i] = *(const float2*)(cp + (y0 - 4 + i) * W);
        float2 e1r[6];
        #pragma unroll
        for (int k = 0; k < 6; k++) e1r[k] = erode5p(c_[k], c_[k + 1], c_[k + 2]);
        float2 e2r[4];
        #pragma unroll
        for (int k = 0; k < 4; k++) e2r[k] = erode5p(e1r[k], e1r[k + 1], e1r[k + 2]);
        e3_m = erode5p(e2r[0], e2r[1], e2r[2]);
        e3_0 = erode5p(e2r[1], e2r[2], e2r[3]);

        c0 = c_[4]; c1 = c_[5]; c2 = c_[6]; c3 = c_[7]; c4 = c_[8]; c5 = c_[9];
        e1_m = e1r[2]; e1_0 = e1r[3]; e1_1 = e1r[4]; e1_2 = e1r[5];
        e2_m = e2r[1]; e2_0 = e2r[2]; e2_1 = e2r[3];

        #pragma unroll 4
        for (int y = y0; y < y0 + SEGH; y++) {
            float2 c6 = *(const float2*)(cp + (y + 6) * W);
            float2 e1_3 = erode5p(c2, c3, c4);
            float2 e2_2 = erode5p(e1_1, e1_2, e1_3);
            float2 e3_1 = erode5p(e2_0, e2_1, e2_2);

            float2 openA = open3p(e2_m, e2_0, e2_1);
            float2 openB = open3p(e3_m, e3_0, e3_1);

            float2 s;
            if (MODE == 0) {
                float2 openI = open3p(e1_m, e1_0, e1_1);
                s.x = fmaxf(c0.x - openI.x, 0.0f);
                s.y = fmaxf(c0.y - openI.y, 0.0f);
            } else {
                s = *(const float2*)(skp + y * W);
            }
            float dA0 = fmaxf(e1_0.x - openA.x, 0.0f);
            float dA1 = fmaxf(e1_0.y - openA.y, 0.0f);
            s.x += fmaxf(dA0 - s.x * dA0, 0.0f);
            s.y += fmaxf(dA1 - s.y * dA1, 0.0f);
            float dB0 = fmaxf(e2_0.x - openB.x, 0.0f);
            float dB1 = fmaxf(e2_0.y - openB.y, 0.0f);
            s.x += fmaxf(dB0 - s.x * dB0, 0.0f);
            s.y += fmaxf(dB1 - s.y * dB1, 0.0f);

            if (MODE == 2) {
                if (laneOut) {
                    float2 t = *(const float2*)(pp + y * W);
                    float t0 = isPred ? fminf(fmaxf(t.x, 0.0f), 1.0f) : sigmoidf_(t.x);
                    float t1 = isPred ? fminf(fmaxf(t.y, 0.0f), 1.0f) : sigmoidf_(t.y);
                    float ps0 = fminf(fmaxf(s.x, 0.0f), 1.0f);
                    float ps1 = fminf(fmaxf(s.y, 0.0f), 1.0f);
                    accP += ps0 * t0 + ps1 * t1;
                    accS += ps0 + ps1;
                }
            } else if (laneOut) {
                *(float2*)(nxp + y * W) = e2_0;
                *(float2*)(skp + y * W) = s;
            }

            if (MODE == 0) { c0 = c1; c1 = c2; }
            c2 = c3; c3 = c4; c4 = c5; c5 = c6;
            if (MODE == 0) e1_m = e1_0;
            e1_0 = e1_1; e1_1 = e1_2; e1_2 = e1_3;
            e2_m = e2_0; e2_0 = e2_1; e2_1 = e2_2;
            e3_m = e3_0; e3_0 = e3_1;
        }
    } else {
        // ---------------- general (boundary) path ----------------
        float2 c_[10];
        #pragma unroll
        for (int i = 0; i < 10; i++) {
            int yy = y0 - 4 + i;
            bool rOK = (unsigned)yy < (unsigned)H;
            float2 v;
            v.x = (rOK && x0OK) ? cp[yy * W] : BIG;
            v.y = (rOK && x1OK) ? cp[yy * W + 1] : BIG;
            c_[i] = v;
        }
        float2 e1r[6];
        #pragma unroll
        for (int k = 0; k < 6; k++) {
            int r = y0 - 3 + k;
            e1r[k] = padv(erode5p(c_[k], c_[k + 1], c_[k + 2]),
                          (unsigned)r < (unsigned)H, x0OK, x1OK, BIG);
        }
        float2 e2r[4];   // raw
        #pragma unroll
        for (int k = 0; k < 4; k++) e2r[k] = erode5p(e1r[k], e1r[k + 1], e1r[k + 2]);

        float2 t0v = padv(e2r[0], (y0 - 2) >= 0, x0OK, x1OK, BIG);
        float2 t1v = padv(e2r[1], (y0 - 1) >= 0, x0OK, x1OK, BIG);
        float2 t2v = padv(e2r[2], true, x0OK, x1OK, BIG);
        float2 t3v = padv(e2r[3], true, x0OK, x1OK, BIG);
        e3_m = padv(erode5p(t0v, t1v, t2v), (y0 - 1) >= 0, x0OK, x1OK, -BIG);
        e3_0 = padv(erode5p(t1v, t2v, t3v), true, x0OK, x1OK, -BIG);

        c0 = c_[4]; c1 = c_[5]; c2 = c_[6]; c3 = c_[7]; c4 = c_[8]; c5 = c_[9];
        e1_m = e1r[2]; e1_0 = e1r[3]; e1_1 = e1r[4]; e1_2 = e1r[5];
        e2_m = e2r[1]; e2_0 = e2r[2]; e2_1 = e2r[3];

        #pragma unroll 4
        for (int y = y0; y < y0 + SEGH; y++) {
            int yl = y + 6;
            bool rl = (unsigned)yl < (unsigned)H;
            float2 c6;
            c6.x = (rl && x0OK) ? cp[yl * W] : BIG;
            c6.y = (rl && x1OK) ? cp[yl * W + 1] : BIG;

            float2 e1_3 = padv(erode5p(c2, c3, c4), (unsigned)(y + 3) < (unsigned)H, x0OK, x1OK, BIG);
            float2 e2_2 = erode5p(e1_1, e1_2, e1_3);

            float2 a = padv(e2_0, true, x0OK, x1OK, BIG);
            float2 b = padv(e2_1, (unsigned)(y + 1) < (unsigned)H, x0OK, x1OK, BIG);
            float2 d = padv(e2_2, (unsigned)(y + 2) < (unsigned)H, x0OK, x1OK, BIG);
            float2 e3_1 = padv(erode5p(a, b, d), (unsigned)(y + 1) < (unsigned)H, x0OK, x1OK, -BIG);

            float2 ma = padv(e2_m, (y - 1) >= 0, x0OK, x1OK, -BIG);
            float2 mb = padv(e2_0, true, x0OK, x1OK, -BIG);
            float2 mc = padv(e2_1, (unsigned)(y + 1) < (unsigned)H, x0OK, x1OK, -BIG);
            float2 openA = open3p(ma, mb, mc);
            float2 openB = open3p(e3_m, e3_0, e3_1);

            float2 s;
            if (MODE == 0) {
                float2 ia = padv(e1_m, (y - 1) >= 0, x0OK, x1OK, -BIG);
                float2 ib = padv(e1_0, true, x0OK, x1OK, -BIG);
                float2 ic = padv(e1_1, (unsigned)(y + 1) < (unsigned)H, x0OK, x1OK, -BIG);
                float2 openI = open3p(ia, ib, ic);
                s.x = fmaxf(c0.x - openI.x, 0.0f);
                s.y = fmaxf(c0.y - openI.y, 0.0f);
            } else {
                s.x = out0 ? skp[y * W] : 0.0f;
                s.y = out1 ? skp[y * W + 1] : 0.0f;
            }
            float dA0 = fmaxf(e1_0.x - openA.x, 0.0f);
            float dA1 = fmaxf(e1_0.y - openA.y, 0.0f);
            s.x += fmaxf(dA0 - s.x * dA0, 0.0f);
            s.y += fmaxf(dA1 - s.y * dA1, 0.0f);
            float dB0 = fmaxf(e2_0.x - openB.x, 0.0f);
            float dB1 = fmaxf(e2_0.y - openB.y, 0.0f);
            s.x += fmaxf(dB0 - s.x * dB0, 0.0f);
            s.y += fmaxf(dB1 - s.y * dB1, 0.0f);

            if (MODE == 2) {
                if (out0) {
                    float raw = pp[y * W];
                    float t = isPred ? fminf(fmaxf(raw, 0.0f), 1.0f) : sigmoidf_(raw);
                    float ps = fminf(fmaxf(s.x, 0.0f), 1.0f);
                    accP += ps * t;  accS += ps;
                }
                if (out1) {
                    float raw = pp[y * W + 1];
                    float t = isPred ? fminf(fmaxf(raw, 0.0f), 1.0f) : sigmoidf_(raw);
                    float ps = fminf(fmaxf(s.y, 0.0f), 1.0f);
                    accP += ps * t;  accS += ps;
                }
            } else {
                if (out0) { nxp[y * W] = e2_0.x;      skp[y * W] = s.x; }
                if (out1) { nxp[y * W + 1] = e2_0.y;  skp[y * W + 1] = s.y; }
            }

            c0 = c1; c1 = c2; c2 = c3; c3 = c4; c4 = c5; c5 = c6;
            e1_m = e1_0; e1_0 = e1_1; e1_1 = e1_2; e1_2 = e1_3;
            e2_m = e2_0; e2_0 = e2_1; e2_1 = e2_2;
            e3_m = e3_0; e3_0 = e3_1;
        }
    }

    if (MODE == 2) {
        #pragma unroll
        for (int o = 16; o > 0; o >>= 1) {
            accP += __shfl_down_sync(0xffffffffu, accP, o);
            accS += __shfl_down_sync(0xffffffffu, accS, o);
        }
        if (lane == 0) {
            int idx = 54 + b8 * 4 + (isPred ? 0 : 2);
            atomicAdd(&g_acc[idx], accP);
            atomicAdd(&g_acc[idx + 1], accS);
        }
    }
}

// ---------------------------------------------------------------------------
__global__ void finalize_kernel(float* __restrict__ out) {
    const float N = (float)NELEM;
    float dice_m = 0.f, dice_s = 0.f, cl = 0.f;
    #pragma unroll
    for (int b = 0; b < NB; b++) {
        float im = g_acc[b * 6 + 0], pm = g_acc[b * 6 + 1], tm = g_acc[b * 6 + 2];
        dice_m += (2.0f * im + EPSF) / (pm + tm + EPSF);
        float is = g_acc[b * 6 + 3], ps = g_acc[b * 6 + 4], ts = g_acc[b * 6 + 5];
        dice_s += (2.0f * is + EPSF) / (ps + ts + EPSF);
        float c0 = g_acc[54 + b * 4 + 0], c1 = g_acc[54 + b * 4 + 1];
        float c2 = g_acc[54 + b * 4 + 2], c3 = g_acc[54 + b * 4 + 3];
        float prec = c0 / (c1 + EPSF);
        float sens = c2 / (c3 + EPSF);
        cl += (2.0f * prec * sens + EPSF) / (prec + sens + EPSF);
    }
    dice_m *= 0.125f;  dice_s *= 0.125f;  cl *= 0.125f;

    float mask_loss     = (1.0f - dice_m) + g_acc[48] / N;
    float skeleton_loss = 1.0f - dice_s;
    float topology_loss = 1.0f - cl;
    float node_loss     = 0.5f * (g_acc[49] / N + g_acc[50] / N);
    float msum          = g_acc[52];
    float aff_loss      = (msum == 0.0f) ? 0.0f : g_acc[51] / fmaxf(msum, 1.0f);
    float unc_loss      = g_acc[53] / N;

    out[0] = 1.0f * mask_loss + 1.0f * skeleton_loss + 0.5f * topology_loss +
             0.5f * node_loss + 0.5f * aff_loss + 0.1f * unc_loss;
}

// ---------------------------------------------------------------------------
extern "C" void kernel_launch(void* const* d_in, const int* in_sizes, int n_in,
                              void* d_out, int out_size) {
    const float* ml = (const float*)d_in[0];
    const float* mk = (const float*)d_in[6];
    float* out = (float*)d_out;

    zero_acc_kernel<<<1, 96>>>();

    dim3 gA(64, NB);
    pass_a_kernel<<<gA, 256>>>(
        (const float4*)d_in[0], (const float4*)d_in[1], (const float4*)d_in[2],
        (const float4*)d_in[3], (const float4*)d_in[4], (const float4*)d_in[5],
        (const float4*)d_in[6], (const float4*)d_in[7], (const float4*)d_in[8],
        (const float4*)d_in[9], (const float4*)d_in[10], (const float4*)d_in[11]);

    // iters 1,2 (init)  A -> B
    skel2_kernel<0><<<GRIDP, 128>>>(1, ml, mk);
    // iters 3,4  B -> A ; 5,6  A -> B ; 7,8  B -> A
    skel2_kernel<1><<<GRIDP, 128>>>(0, ml, mk);
    skel2_kernel<1><<<GRIDP, 128>>>(1, ml, mk);
    skel2_kernel<1><<<GRIDP, 128>>>(0, ml, mk);
    // iters 9,10 + clDice reduce, read A, no writes
    skel2_kernel<2><<<GRIDP, 128>>>(1, ml, mk);

    finalize_kernel<<<1, 1>>>(out);
}

// round 13
// speedup vs baseline: 1.3433x; 1.0199x over previous
#include <cuda_runtime.h>
#include <math.h>

#define H 512
#define W 512
#define PLANE (H*W)
#define NB 8
#define NPL 16
#define NELEM (NB*PLANE)
#define EPSF 1e-6f
#define BIG 1e30f

// 2-col-per-thread skeletonize layout: 56 useful cols per warp, 16 rows per seg
#define STRIPSP 10
#define SEGSP   32
#define SEGH    16
#define BLK_WARPS 4
#define PL_CHUNK 4                       // planes per stream chain
#define WARPS_CHAIN (PL_CHUNK*STRIPSP*SEGSP)   // 1280
#define GRIDC  (WARPS_CHAIN/BLK_WARPS)   // 320 blocks per chain launch

__device__ float g_bufA[NPL*PLANE];
__device__ float g_bufB[NPL*PLANE];
__device__ float g_skel[NPL*PLANE];
__device__ float g_acc[96];

// fast sigmoid: sigmoid(x) = 0.5*tanh(x/2) + 0.5  (MUFU.TANH, sm_75+)
__device__ __forceinline__ float sigmoidf_(float x) {
    float t;
    asm("tanh.approx.f32 %0, %1;" : "=f"(t) : "f"(0.5f * x));
    return fmaf(0.5f, t, 0.5f);
}

__device__ __forceinline__ float focal_elem(float x, float t) {
    float e = __expf(-fabsf(x));
    float bce = fmaxf(x, 0.0f) - x * t + __logf(1.0f + e);
    float p   = sigmoidf_(x);
    float pt  = p * t + (1.0f - p) * (1.0f - t);
    float at  = 0.25f * t + 0.75f * (1.0f - t);
    float om  = 1.0f - pt;
    return at * om * om * bce;
}

__device__ __forceinline__ float blk_sum(float v, float* sh) {
    int tid = threadIdx.x;
    #pragma unroll
    for (int o = 16; o > 0; o >>= 1) v += __shfl_down_sync(0xffffffffu, v, o);
    if ((tid & 31) == 0) sh[tid >> 5] = v;
    __syncthreads();
    float r = 0.0f;
    if (tid < 32) {
        r = (tid < (int)(blockDim.x >> 5)) ? sh[tid] : 0.0f;
        #pragma unroll
        for (int o = 16; o > 0; o >>= 1) r += __shfl_down_sync(0xffffffffu, r, o);
    }
    __syncthreads();
    return r;
}

// pairwise 5-pt cross erode over 64 warp columns (cols x0=2*lane, x1=2*lane+1)
__device__ __forceinline__ float2 erode5p(float2 m, float2 c, float2 p) {
    float lm = __shfl_up_sync(0xffffffffu, c.y, 1);
    float rm = __shfl_down_sync(0xffffffffu, c.x, 1);
    float2 r;
    r.x = fminf(fminf(fminf(m.x, p.x), c.x), fminf(lm, c.y));
    r.y = fminf(fminf(fminf(m.y, p.y), c.y), fminf(c.x, rm));
    return r;
}
// pairwise 3x3 max (open)
__device__ __forceinline__ float2 open3p(float2 m, float2 c, float2 p) {
    float2 v;
    v.x = fmaxf(fmaxf(m.x, p.x), c.x);
    v.y = fmaxf(fmaxf(m.y, p.y), c.y);
    float lm = __shfl_up_sync(0xffffffffu, v.y, 1);
    float rm = __shfl_down_sync(0xffffffffu, v.x, 1);
    float2 r;
    r.x = fmaxf(v.x, fmaxf(lm, v.y));
    r.y = fmaxf(v.y, fmaxf(v.x, rm));
    return r;
}
__device__ __forceinline__ float2 padv(float2 v, bool rowOK, bool x0OK, bool x1OK, float pad) {
    float2 r;
    r.x = (rowOK && x0OK) ? v.x : pad;
    r.y = (rowOK && x1OK) ? v.y : pad;
    return r;
}

__global__ void zero_acc_kernel() {
    if (threadIdx.x < 96) g_acc[threadIdx.x] = 0.0f;
}

// ---------------------------------------------------------------------------
// Pass A (float4-vectorized); seeds g_bufA only.
// ---------------------------------------------------------------------------
__global__ void pass_a_kernel(const float4* __restrict__ ml, const float4* __restrict__ sl,
                              const float4* __restrict__ ul, const float4* __restrict__ jl,
                              const float4* __restrict__ el, const float4* __restrict__ ap,
                              const float4* __restrict__ mk, const float4* __restrict__ sk,
                              const float4* __restrict__ jn, const float4* __restrict__ ep,
                              const float4* __restrict__ at, const float4* __restrict__ un) {
    const int Q = PLANE / 4;
    int b   = blockIdx.y;
    int tid = threadIdx.x;
    int base = b * Q;

    float4* __restrict__ bufap = (float4*)g_bufA;

    float di = 0.f, dp = 0.f, dt = 0.f;
    float si = 0.f, spp = 0.f, stt = 0.f;
    float fm = 0.f, fj = 0.f, fe = 0.f;
    float sl1 = 0.f, msum = 0.f, usum = 0.f;

    for (int i = blockIdx.x * blockDim.x + tid; i < Q; i += gridDim.x * blockDim.x) {
        int g = base + i;
        float4 xm4 = ml[g];
        float4 tm4 = mk[g];
        float4 pm4, tmc4;

        #pragma unroll
        for (int u = 0; u < 4; u++) {
            float xm = ((float*)&xm4)[u];
            float tm = ((float*)&tm4)[u];
            float pm = sigmoidf_(xm);
            ((float*)&pm4)[u] = pm;
            ((float*)&tmc4)[u] = fminf(fmaxf(tm, 0.0f), 1.0f);
            di += pm * tm;  dp += pm;  dt += tm;
            fm += focal_elem(xm, tm);
        }
        bufap[g] = pm4;
        bufap[(8 + b) * Q + i] = tmc4;

        float4 ts4 = sk[g];
        float4 ps4 = sl[g];
        float4 jl4 = jl[g], jn4 = jn[g], el4 = el[g], ep4 = ep[g];
        float4 ul4 = ul[g], un4 = un[g];
        float4 ap0 = ap[b * 2 * Q + i], ap1 = ap[b * 2 * Q + Q + i];
        float4 at0 = at[b * 2 * Q + i], at1 = at[b * 2 * Q + Q + i];

        #pragma unroll
        for (int u = 0; u < 4; u++) {
            float ts = ((float*)&ts4)[u];
            float psk = sigmoidf_(((float*)&ps4)[u]);
            si += psk * ts;  spp += psk;  stt += ts;

            fj += focal_elem(((float*)&jl4)[u], ((float*)&jn4)[u]);
            fe += focal_elem(((float*)&el4)[u], ((float*)&ep4)[u]);

            float pu = sigmoidf_(((float*)&ul4)[u]);
            float du = pu - ((float*)&un4)[u];
            usum += du * du;

            float m = ts;
            float d0 = ((float*)&ap0)[u] * m - ((float*)&at0)[u] * m;
            float ad0 = fabsf(d0);
            sl1 += (ad0 < 1.0f) ? 0.5f * d0 * d0 : ad0 - 0.5f;
            float d1 = ((float*)&ap1)[u] * m - ((float*)&at1)[u] * m;
            float ad1 = fabsf(d1);
            sl1 += (ad1 < 1.0f) ? 0.5f * d1 * d1 : ad1 - 0.5f;
            msum += 2.0f * m;
        }
    }

    __shared__ float sh[32];
    float vals[12] = {di, dp, dt, si, spp, stt, fm, fj, fe, sl1, msum, usum};
    #pragma unroll
    for (int k = 0; k < 12; k++) {
        float r = blk_sum(vals[k], sh);
        if (tid == 0) {
            int a = (k < 6) ? (b * 6 + k) : (42 + k);
            atomicAdd(&g_acc[a], r);
        }
    }
}

// ---------------------------------------------------------------------------
// Fused double-iteration skeletonize, 2 columns per thread, per-chain grids.
//  MODE 0: init + iters 1,2  (skel pure write)
//  MODE 1: two iterations     (skel RMW)
//  MODE 2: final two iters + clDice accumulation (no global writes)
//  planeBase: first plane of this chain (grid covers PL_CHUNK planes)
// ---------------------------------------------------------------------------
template<int MODE>
__global__ void __launch_bounds__(128, 9) skel2_kernel(int useA, int planeBase,
                                                       const float* __restrict__ ml,
                                                       const float* __restrict__ mk) {
    const float* __restrict__ cur = useA ? g_bufA : g_bufB;
    float* __restrict__ nxt = useA ? g_bufB : g_bufA;

    int lane = threadIdx.x & 31;
    int wg = blockIdx.x * BLK_WARPS + (threadIdx.x >> 5);
    int plane = planeBase + wg / (STRIPSP * SEGSP);
    int rem = wg % (STRIPSP * SEGSP);
    int strip = rem / SEGSP;
    int seg = rem & (SEGSP - 1);

    int x0 = strip * 56 - 4 + 2 * lane;       // even
    int x1 = x0 + 1;
    bool x0OK = (unsigned)x0 < (unsigned)W;
    bool x1OK = (unsigned)x1 < (unsigned)W;
    bool laneOut = (lane >= 2) && (lane <= 29);
    bool out0 = laneOut && x0OK;
    bool out1 = laneOut && x1OK;
    int y0 = seg * SEGH;
    int base = plane * PLANE;

    const float* __restrict__ cp = cur + base + x0;
    float* __restrict__ skp = g_skel + base + x0;
    float* __restrict__ nxp = nxt + base + x0;

    // clDice partner source (MODE 2): plane<8 -> clip(mask), plane>=8 -> sigmoid(mask_logits)
    bool isPred = (plane < 8);
    int b8 = isPred ? plane : (plane - 8);
    const float* __restrict__ pp = (isPred ? mk : ml) + b8 * PLANE + x0;
    float accP = 0.0f, accS = 0.0f;

    bool fast = (strip >= 1) && (strip <= 8) && (seg >= 1) && (seg <= 30);

    float2 c0, c1, c2, c3, c4, c5;
    float2 e1_m, e1_0, e1_1, e1_2;
    float2 e2_m, e2_0, e2_1;
    float2 e3_m, e3_0;

    if (fast) {
        float2 c_[10];
        #pragma unroll
        for (int i = 0; i < 10; i++) c_[i] = *(const float2*)(cp + (y0 - 4 + i) * W);
        float2 e1r[6];
        #pragma unroll
        for (int k = 0; k < 6; k++) e1r[k] = erode5p(c_[k], c_[k + 1], c_[k + 2]);
        float2 e2r[4];
        #pragma unroll
        for (int k = 0; k < 4; k++) e2r[k] = erode5p(e1r[k], e1r[k + 1], e1r[k + 2]);
        e3_m = erode5p(e2r[0], e2r[1], e2r[2]);
        e3_0 = erode5p(e2r[1], e2r[2], e2r[3]);

        c0 = c_[4]; c1 = c_[5]; c2 = c_[6]; c3 = c_[7]; c4 = c_[8]; c5 = c_[9];
        e1_m = e1r[2]; e1_0 = e1r[3]; e1_1 = e1r[4]; e1_2 = e1r[5];
        e2_m = e2r[1]; e2_0 = e2r[2]; e2_1 = e2r[3];

        #pragma unroll 4
        for (int y = y0; y < y0 + SEGH; y++) {
            float2 c6 = *(const float2*)(cp + (y + 6) * W);
            float2 e1_3 = erode5p(c2, c3, c4);
            float2 e2_2 = erode5p(e1_1, e1_2, e1_3);
            float2 e3_1 = erode5p(e2_0, e2_1, e2_2);

            float2 openA = open3p(e2_m, e2_0, e2_1);
            float2 openB = open3p(e3_m, e3_0, e3_1);

            float2 s;
            if (MODE == 0) {
                float2 openI = open3p(e1_m, e1_0, e1_1);
                s.x = fmaxf(c0.x - openI.x, 0.0f);
                s.y = fmaxf(c0.y - openI.y, 0.0f);
            } else {
                s = *(const float2*)(skp + y * W);
            }
            float dA0 = fmaxf(e1_0.x - openA.x, 0.0f);
            float dA1 = fmaxf(e1_0.y - openA.y, 0.0f);
            s.x += fmaxf(dA0 - s.x * dA0, 0.0f);
            s.y += fmaxf(dA1 - s.y * dA1, 0.0f);
            float dB0 = fmaxf(e2_0.x - openB.x, 0.0f);
            float dB1 = fmaxf(e2_0.y - openB.y, 0.0f);
            s.x += fmaxf(dB0 - s.x * dB0, 0.0f);
            s.y += fmaxf(dB1 - s.y * dB1, 0.0f);

            if (MODE == 2) {
                if (laneOut) {
                    float2 t = *(const float2*)(pp + y * W);
                    float t0 = isPred ? fminf(fmaxf(t.x, 0.0f), 1.0f) : sigmoidf_(t.x);
                    float t1 = isPred ? fminf(fmaxf(t.y, 0.0f), 1.0f) : sigmoidf_(t.y);
                    float ps0 = fminf(fmaxf(s.x, 0.0f), 1.0f);
                    float ps1 = fminf(fmaxf(s.y, 0.0f), 1.0f);
                    accP += ps0 * t0 + ps1 * t1;
                    accS += ps0 + ps1;
                }
            } else if (laneOut) {
                *(float2*)(nxp + y * W) = e2_0;
                *(float2*)(skp + y * W) = s;
            }

            if (MODE == 0) { c0 = c1; c1 = c2; }
            c2 = c3; c3 = c4; c4 = c5; c5 = c6;
            if (MODE == 0) e1_m = e1_0;
            e1_0 = e1_1; e1_1 = e1_2; e1_2 = e1_3;
            e2_m = e2_0; e2_0 = e2_1; e2_1 = e2_2;
            e3_m = e3_0; e3_0 = e3_1;
        }
    } else {
        // ---------------- general (boundary) path ----------------
        float2 c_[10];
        #pragma unroll
        for (int i = 0; i < 10; i++) {
            int yy = y0 - 4 + i;
            bool rOK = (unsigned)yy < (unsigned)H;
            float2 v;
            v.x = (rOK && x0OK) ? cp[yy * W] : BIG;
            v.y = (rOK && x1OK) ? cp[yy * W + 1] : BIG;
            c_[i] = v;
        }
        float2 e1r[6];
        #pragma unroll
        for (int k = 0; k < 6; k++) {
            int r = y0 - 3 + k;
            e1r[k] = padv(erode5p(c_[k], c_[k + 1], c_[k + 2]),
                          (unsigned)r < (unsigned)H, x0OK, x1OK, BIG);
        }
        float2 e2r[4];   // raw
        #pragma unroll
        for (int k = 0; k < 4; k++) e2r[k] = erode5p(e1r[k], e1r[k + 1], e1r[k + 2]);

        float2 t0v = padv(e2r[0], (y0 - 2) >= 0, x0OK, x1OK, BIG);
        float2 t1v = padv(e2r[1], (y0 - 1) >= 0, x0OK, x1OK, BIG);
        float2 t2v = padv(e2r[2], true, x0OK, x1OK, BIG);
        float2 t3v = padv(e2r[3], true, x0OK, x1OK, BIG);
        e3_m = padv(erode5p(t0v, t1v, t2v), (y0 - 1) >= 0, x0OK, x1OK, -BIG);
        e3_0 = padv(erode5p(t1v, t2v, t3v), true, x0OK, x1OK, -BIG);

        c0 = c_[4]; c1 = c_[5]; c2 = c_[6]; c3 = c_[7]; c4 = c_[8]; c5 = c_[9];
        e1_m = e1r[2]; e1_0 = e1r[3]; e1_1 = e1r[4]; e1_2 = e1r[5];
        e2_m = e2r[1]; e2_0 = e2r[2]; e2_1 = e2r[3];

        #pragma unroll 4
        for (int y = y0; y < y0 + SEGH; y++) {
            int yl = y + 6;
            bool rl = (unsigned)yl < (unsigned)H;
            float2 c6;
            c6.x = (rl && x0OK) ? cp[yl * W] : BIG;
            c6.y = (rl && x1OK) ? cp[yl * W + 1] : BIG;

            float2 e1_3 = padv(erode5p(c2, c3, c4), (unsigned)(y + 3) < (unsigned)H, x0OK, x1OK, BIG);
            float2 e2_2 = erode5p(e1_1, e1_2, e1_3);

            float2 a = padv(e2_0, true, x0OK, x1OK, BIG);
            float2 b = padv(e2_1, (unsigned)(y + 1) < (unsigned)H, x0OK, x1OK, BIG);
            float2 d = padv(e2_2, (unsigned)(y + 2) < (unsigned)H, x0OK, x1OK, BIG);
            float2 e3_1 = padv(erode5p(a, b, d), (unsigned)(y + 1) < (unsigned)H, x0OK, x1OK, -BIG);

            float2 ma = padv(e2_m, (y - 1) >= 0, x0OK, x1OK, -BIG);
            float2 mb = padv(e2_0, true, x0OK, x1OK, -BIG);
            float2 mc = padv(e2_1, (unsigned)(y + 1) < (unsigned)H, x0OK, x1OK, -BIG);
            float2 openA = open3p(ma, mb, mc);
            float2 openB = open3p(e3_m, e3_0, e3_1);

            float2 s;
            if (MODE == 0) {
                float2 ia = padv(e1_m, (y - 1) >= 0, x0OK, x1OK, -BIG);
                float2 ib = padv(e1_0, true, x0OK, x1OK, -BIG);
                float2 ic = padv(e1_1, (unsigned)(y + 1) < (unsigned)H, x0OK, x1OK, -BIG);
                float2 openI = open3p(ia, ib, ic);
                s.x = fmaxf(c0.x - openI.x, 0.0f);
                s.y = fmaxf(c0.y - openI.y, 0.0f);
            } else {
                s.x = out0 ? skp[y * W] : 0.0f;
                s.y = out1 ? skp[y * W + 1] : 0.0f;
            }
            float dA0 = fmaxf(e1_0.x - openA.x, 0.0f);
            float dA1 = fmaxf(e1_0.y - openA.y, 0.0f);
            s.x += fmaxf(dA0 - s.x * dA0, 0.0f);
            s.y += fmaxf(dA1 - s.y * dA1, 0.0f);
            float dB0 = fmaxf(e2_0.x - openB.x, 0.0f);
            float dB1 = fmaxf(e2_0.y - openB.y, 0.0f);
            s.x += fmaxf(dB0 - s.x * dB0, 0.0f);
            s.y += fmaxf(dB1 - s.y * dB1, 0.0f);

            if (MODE == 2) {
                if (out0) {
                    float raw = pp[y * W];
                    float t = isPred ? fminf(fmaxf(raw, 0.0f), 1.0f) : sigmoidf_(raw);
                    float ps = fminf(fmaxf(s.x, 0.0f), 1.0f);
                    accP += ps * t;  accS += ps;
                }
                if (out1) {
                    float raw = pp[y * W + 1];
                    float t = isPred ? fminf(fmaxf(raw, 0.0f), 1.0f) : sigmoidf_(raw);
                    float ps = fminf(fmaxf(s.y, 0.0f), 1.0f);
                    accP += ps * t;  accS += ps;
                }
            } else {
                if (out0) { nxp[y * W] = e2_0.x;      skp[y * W] = s.x; }
                if (out1) { nxp[y * W + 1] = e2_0.y;  skp[y * W + 1] = s.y; }
            }

            c0 = c1; c1 = c2; c2 = c3; c3 = c4; c4 = c5; c5 = c6;
            e1_m = e1_0; e1_0 = e1_1; e1_1 = e1_2; e1_2 = e1_3;
            e2_m = e2_0; e2_0 = e2_1; e2_1 = e2_2;
            e3_m = e3_0; e3_0 = e3_1;
        }
    }

    if (MODE == 2) {
        #pragma unroll
        for (int o = 16; o > 0; o >>= 1) {
            accP += __shfl_down_sync(0xffffffffu, accP, o);
            accS += __shfl_down_sync(0xffffffffu, accS, o);
        }
        if (lane == 0) {
            int idx = 54 + b8 * 4 + (isPred ? 0 : 2);
            atomicAdd(&g_acc[idx], accP);
            atomicAdd(&g_acc[idx + 1], accS);
        }
    }
}

// ---------------------------------------------------------------------------
__global__ void finalize_kernel(float* __restrict__ out) {
    const float N = (float)NELEM;
    float dice_m = 0.f, dice_s = 0.f, cl = 0.f;
    #pragma unroll
    for (int b = 0; b < NB; b++) {
        float im = g_acc[b * 6 + 0], pm = g_acc[b * 6 + 1], tm = g_acc[b * 6 + 2];
        dice_m += (2.0f * im + EPSF) / (pm + tm + EPSF);
        float is = g_acc[b * 6 + 3], ps = g_acc[b * 6 + 4], ts = g_acc[b * 6 + 5];
        dice_s += (2.0f * is + EPSF) / (ps + ts + EPSF);
        float c0 = g_acc[54 + b * 4 + 0], c1 = g_acc[54 + b * 4 + 1];
        float c2 = g_acc[54 + b * 4 + 2], c3 = g_acc[54 + b * 4 + 3];
        float prec = c0 / (c1 + EPSF);
        float sens = c2 / (c3 + EPSF);
        cl += (2.0f * prec * sens + EPSF) / (prec + sens + EPSF);
    }
    dice_m *= 0.125f;  dice_s *= 0.125f;  cl *= 0.125f;

    float mask_loss     = (1.0f - dice_m) + g_acc[48] / N;
    float skeleton_loss = 1.0f - dice_s;
    float topology_loss = 1.0f - cl;
    float node_loss     = 0.5f * (g_acc[49] / N + g_acc[50] / N);
    float msum          = g_acc[52];
    float aff_loss      = (msum == 0.0f) ? 0.0f : g_acc[51] / fmaxf(msum, 1.0f);
    float unc_loss      = g_acc[53] / N;

    out[0] = 1.0f * mask_loss + 1.0f * skeleton_loss + 0.5f * topology_loss +
             0.5f * node_loss + 0.5f * aff_loss + 0.1f * unc_loss;
}

// ---------------------------------------------------------------------------
extern "C" void kernel_launch(void* const* d_in, const int* in_sizes, int n_in,
                              void* d_out, int out_size) {
    const float* ml = (const float*)d_in[0];
    const float* mk = (const float*)d_in[6];
    float* out = (float*)d_out;

    zero_acc_kernel<<<1, 96>>>();

    dim3 gA(64, NB);
    pass_a_kernel<<<gA, 256>>>(
        (const float4*)d_in[0], (const float4*)d_in[1], (const float4*)d_in[2],
        (const float4*)d_in[3], (const float4*)d_in[4], (const float4*)d_in[5],
        (const float4*)d_in[6], (const float4*)d_in[7], (const float4*)d_in[8],
        (const float4*)d_in[9], (const float4*)d_in[10], (const float4*)d_in[11]);

    // ---- fork 4 independent plane-chains onto side streams ----
    const int NCH = 4;
    cudaStream_t st[NCH];
    cudaEvent_t evFork, evJoin[NCH];
    cudaEventCreateWithFlags(&evFork, cudaEventDisableTiming);
    cudaEventRecord(evFork, 0);

    for (int c = 0; c < NCH; c++) {
        cudaStreamCreateWithFlags(&st[c], cudaStreamNonBlocking);
        cudaEventCreateWithFlags(&evJoin[c], cudaEventDisableTiming);
        cudaStreamWaitEvent(st[c], evFork, 0);
        int pb = c * PL_CHUNK;
        // iters 1,2 (init)  A -> B
        skel2_kernel<0><<<GRIDC, 128, 0, st[c]>>>(1, pb, ml, mk);
        // iters 3,4  B -> A ; 5,6  A -> B ; 7,8  B -> A
        skel2_kernel<1><<<GRIDC, 128, 0, st[c]>>>(0, pb, ml, mk);
        skel2_kernel<1><<<GRIDC, 128, 0, st[c]>>>(1, pb, ml, mk);
        skel2_kernel<1><<<GRIDC, 128, 0, st[c]>>>(0, pb, ml, mk);
        // iters 9,10 + clDice reduce, read A, no writes
        skel2_kernel<2><<<GRIDC, 128, 0, st[c]>>>(1, pb, ml, mk);
        cudaEventRecord(evJoin[c], st[c]);
    }
    for (int c = 0; c < NCH; c++) {
        cudaStreamWaitEvent(0, evJoin[c], 0);
    }

    finalize_kernel<<<1, 1>>>(out);

    for (int c = 0; c < NCH; c++) {
        cudaStreamDestroy(st[c]);
        cudaEventDestroy(evJoin[c]);
    }
    cudaEventDestroy(evFork);
}